// round 13
// baseline (speedup 1.0000x reference)
#include <cuda_runtime.h>
#include <cuda_bf16.h>
#include <math.h>
#include <stdint.h>

#define NE 200000
#define NU 100000
#define NEDGE 1000000
#define HDIM 128

// ---------------- scratch (static device arrays; no allocation) ----------------
__device__ float g_xe[(size_t)NE * HDIM];
__device__ float g_accE[(size_t)NE * HDIM];
__device__ float g_accE2[(size_t)NE * HDIM];
__device__ float g_e1[(size_t)NE * HDIM];
__device__ float g_accU[(size_t)NU * HDIM];
__device__ float g_u1[(size_t)NU * HDIM];
__device__ float g_h[(size_t)NE * 64];
__device__ float g_cntE[NE];
__device__ float g_cntU[NU];
// bf16 hi/lo weight tiles, padded row stride 136 (272B -> conflict-free ldmatrix)
#define WSTRIDE 136
__device__ __align__(16) __nv_bfloat16 g_weh[128 * WSTRIDE];
__device__ __align__(16) __nv_bfloat16 g_wel[128 * WSTRIDE];
__device__ __align__(16) __nv_bfloat16 g_wh[6][128 * WSTRIDE];
__device__ __align__(16) __nv_bfloat16 g_wl[6][128 * WSTRIDE];

// ---------------- helpers ----------------
__device__ __forceinline__ void fma_x2(unsigned long long& acc, unsigned long long a,
                                       unsigned long long b) {
    asm("fma.rn.f32x2 %0, %1, %2, %0;" : "+l"(acc) : "l"(a), "l"(b));
}
__device__ __forceinline__ unsigned long long dup_x2(float v) {
    unsigned long long r;
    asm("mov.b64 %0, {%1, %1};" : "=l"(r) : "f"(v));
    return r;
}
__device__ __forceinline__ void unpack_x2(unsigned long long v, float& lo, float& hi) {
    asm("mov.b64 {%0, %1}, %2;" : "=f"(lo), "=f"(hi) : "l"(v));
}
__device__ __forceinline__ uint32_t smem_u32(const void* p) {
    return (uint32_t)__cvta_generic_to_shared(p);
}
__device__ __forceinline__ void cp_async16(uint32_t dst, const void* src) {
    asm volatile("cp.async.ca.shared.global [%0], [%1], 16;" :: "r"(dst), "l"(src));
}
__device__ __forceinline__ void cp_commit() { asm volatile("cp.async.commit_group;"); }
__device__ __forceinline__ void cp_wait_all() {
    asm volatile("cp.async.wait_group 0;" ::: "memory");
}
__device__ __forceinline__ uint32_t pack_bf16(__nv_bfloat16 a, __nv_bfloat16 b) {
    uint16_t ua = *(uint16_t*)&a, ub = *(uint16_t*)&b;
    return (uint32_t)ua | ((uint32_t)ub << 16);
}
__device__ __forceinline__ void ldsm_x4(uint32_t r[4], uint32_t addr) {
    asm volatile("ldmatrix.sync.aligned.m8n8.x4.shared.b16 {%0,%1,%2,%3}, [%4];"
                 : "=r"(r[0]), "=r"(r[1]), "=r"(r[2]), "=r"(r[3]) : "r"(addr));
}
__device__ __forceinline__ void mma_bf16(float d[4], const uint32_t a[4],
                                         uint32_t b0, uint32_t b1) {
    asm volatile(
        "mma.sync.aligned.m16n8k16.row.col.f32.bf16.bf16.f32 "
        "{%0,%1,%2,%3}, {%4,%5,%6,%7}, {%8,%9}, {%0,%1,%2,%3};"
        : "+f"(d[0]), "+f"(d[1]), "+f"(d[2]), "+f"(d[3])
        : "r"(a[0]), "r"(a[1]), "r"(a[2]), "r"(a[3]), "r"(b0), "r"(b1));
}

// fragment bank for one k-step (12 ldmatrix.x4 results)
struct Frag {
    uint32_t ah[2][4], al[2][4];
    uint32_t bh[4][4], bl[4][4];
};

// ---------------- init: zero accumulators + split weights to bf16 hi/lo ----------
__global__ void init_kernel(const float* we, const float* w1n, const float* w1r,
                            const float* w2n, const float* w2r,
                            const float* w3n, const float* w3r)
{
    int i = blockIdx.x * blockDim.x + threadIdx.x;
    int stride = gridDim.x * blockDim.x;
    const int nE4 = NE * HDIM / 4, nU4 = NU * HDIM / 4;
    const int cE4 = NE / 4, cU4 = NU / 4;
    float4 z = make_float4(0.f, 0.f, 0.f, 0.f);
    float4* aE  = (float4*)g_accE;
    float4* aE2 = (float4*)g_accE2;
    float4* aU  = (float4*)g_accU;
    for (int k = i; k < nE4; k += stride) { aE[k] = z; aE2[k] = z; }
    for (int k = i; k < nU4; k += stride) aU[k] = z;
    for (int k = i; k < cE4; k += stride) ((float4*)g_cntE)[k] = z;
    for (int k = i; k < cU4; k += stride) ((float4*)g_cntU)[k] = z;
    for (int k = i; k < 128 * 64; k += stride) {
        int n = k >> 6, c = k & 63;
        float w = we[n * 64 + c];
        __nv_bfloat16 h = __float2bfloat16(w);
        __nv_bfloat16 l = __float2bfloat16(w - __bfloat162float(h));
        g_weh[n * WSTRIDE + c] = h;
        g_wel[n * WSTRIDE + c] = l;
    }
    for (int k = i; k < 6 * 128 * 128; k += stride) {
        int m = k >> 14, r = k & 16383;
        int n = r >> 7, c = r & 127;
        const float* src;
        switch (m) {
            case 0: src = w1n; break;
            case 1: src = w1r; break;
            case 2: src = w2n; break;
            case 3: src = w2r; break;
            case 4: src = w3n; break;
            default: src = w3r; break;
        }
        float w = src[n * 128 + c];
        __nv_bfloat16 h = __float2bfloat16(w);
        __nv_bfloat16 l = __float2bfloat16(w - __bfloat162float(h));
        g_wh[m][n * WSTRIDE + c] = h;
        g_wl[m][n * WSTRIDE + c] = l;
    }
}

// ---------------- edge scatter: one warp per 8 edges (MLP=8), vector RED --------
__global__ void scatter_kernel(const int* __restrict__ src, const int* __restrict__ dst,
                               const float* __restrict__ xsrc,
                               float* __restrict__ accum, float* __restrict__ cnt,
                               int doCnt)
{
    int warp = (blockIdx.x * blockDim.x + threadIdx.x) >> 5;
    int lane = threadIdx.x & 31;
    int e0 = warp * 8;
    if (e0 >= NEDGE) return;
    int4 sa = *reinterpret_cast<const int4*>(src + e0);
    int4 sb = *reinterpret_cast<const int4*>(src + e0 + 4);
    int4 da = *reinterpret_cast<const int4*>(dst + e0);
    int4 db = *reinterpret_cast<const int4*>(dst + e0 + 4);
    int s[8] = {sa.x, sa.y, sa.z, sa.w, sb.x, sb.y, sb.z, sb.w};
    int d[8] = {da.x, da.y, da.z, da.w, db.x, db.y, db.z, db.w};
    float4 v[8];
#pragma unroll
    for (int i = 0; i < 8; i++)
        v[i] = *reinterpret_cast<const float4*>(xsrc + (size_t)s[i] * HDIM + lane * 4);
#pragma unroll
    for (int i = 0; i < 8; i++) {
        float* a = accum + (size_t)d[i] * HDIM + lane * 4;
        asm volatile("red.global.add.v4.f32 [%0], {%1, %2, %3, %4};"
                     :: "l"(a), "f"(v[i].x), "f"(v[i].y), "f"(v[i].z), "f"(v[i].w) : "memory");
    }
    if (doCnt && lane == 0) {
#pragma unroll
        for (int i = 0; i < 8; i++) {
            float one = 1.0f;
            asm volatile("red.global.add.f32 [%0], %1;" :: "l"(cnt + d[i]), "f"(one) : "memory");
        }
    }
}

// ---------------- tensor-core combine GEMM (mma.sync bf16-split, pipelined) ------
// out[M,128] = epi( (A1*diag(1/max(cnt,1)) if MEAN) @ W1^T
//                   + (HAS_A2 ? A2 @ W2^T : 0) + bias ),  relu if RELU
// 8 warps: warp w owns rows (w>>1)*32..+31 x cols (w&1)*64..+63.
// K-loop software pipelined: prefetch k-step ks+1 fragments during ks MMAs.
#define TILEB 34816u
template<bool HAS_A2, bool RELU, bool MEAN>
__global__ void __launch_bounds__(256)
gemm_tc(const float* __restrict__ A1, int K1,
        const __nv_bfloat16* __restrict__ W1h, const __nv_bfloat16* __restrict__ W1l,
        const float* __restrict__ A2,
        const __nv_bfloat16* __restrict__ W2h, const __nv_bfloat16* __restrict__ W2l,
        const float* __restrict__ bias, const float* __restrict__ cnt,
        float* __restrict__ out, int M)
{
    extern __shared__ char dsm[];
    uint32_t smBase = smem_u32(dsm);
    const uint32_t offAH = 0, offAL = TILEB;
    const uint32_t offW1h = 2 * TILEB, offW1l = 3 * TILEB;
    const uint32_t offW2h = 4 * TILEB, offW2l = 5 * TILEB;

    int tid = threadIdx.x;
    int widx = tid >> 5, lane = tid & 31;
    int rb = widx >> 1;          // row block 0..3 (32 rows each)
    int cb = widx & 1;           // col block 0..1 (64 cols each)
    int row0 = blockIdx.x * 128;

    // async W tile copies (padded layout pre-baked in gmem)
    {
        for (uint32_t i = tid * 16; i < TILEB; i += 256 * 16) {
            cp_async16(smBase + offW1h + i, (const char*)W1h + i);
            cp_async16(smBase + offW1l + i, (const char*)W1l + i);
        }
        if (HAS_A2) {
            for (uint32_t i = tid * 16; i < TILEB; i += 256 * 16) {
                cp_async16(smBase + offW2h + i, (const char*)W2h + i);
                cp_async16(smBase + offW2l + i, (const char*)W2l + i);
            }
        }
        cp_commit();
    }

    // A fp32 -> (hi,lo) bf16 conversion into smem tiles; 1/cnt folded if mean
    auto convA = [&](const float* A, int K, bool mean) {
        int r = tid >> 1;
        int half = tid & 1;
        int cw = K >> 1;
        int c0 = half * cw;
        int gr = row0 + r;
        float inv = 1.f;
        if (mean) {
            float cv = (gr < M) ? cnt[gr] : 1.f;
            inv = 1.f / fmaxf(cv, 1.f);
        }
        const float* Arow = A + (size_t)gr * K;
        char* pH = dsm + offAH + (uint32_t)r * 272u;
        char* pL = dsm + offAL + (uint32_t)r * 272u;
        for (int c = c0; c < c0 + cw; c += 4) {
            float4 a = make_float4(0.f, 0.f, 0.f, 0.f);
            if (gr < M) a = *reinterpret_cast<const float4*>(Arow + c);
            float v0 = a.x * inv, v1 = a.y * inv, v2 = a.z * inv, v3 = a.w * inv;
            __nv_bfloat16 h0 = __float2bfloat16(v0), h1 = __float2bfloat16(v1);
            __nv_bfloat16 h2 = __float2bfloat16(v2), h3 = __float2bfloat16(v3);
            __nv_bfloat16 l0 = __float2bfloat16(v0 - __bfloat162float(h0));
            __nv_bfloat16 l1 = __float2bfloat16(v1 - __bfloat162float(h1));
            __nv_bfloat16 l2 = __float2bfloat16(v2 - __bfloat162float(h2));
            __nv_bfloat16 l3 = __float2bfloat16(v3 - __bfloat162float(h3));
            *(uint32_t*)(pH + c * 2)     = pack_bf16(h0, h1);
            *(uint32_t*)(pH + c * 2 + 4) = pack_bf16(h2, h3);
            *(uint32_t*)(pL + c * 2)     = pack_bf16(l0, l1);
            *(uint32_t*)(pL + c * 2 + 4) = pack_bf16(l2, l3);
        }
    };

    float acc[16][4];
#pragma unroll
    for (int t = 0; t < 16; t++)
#pragma unroll
        for (int q = 0; q < 4; q++) acc[t][q] = 0.f;

    // per-lane ldmatrix address components
    uint32_t aRowL = (uint32_t)(lane & 15);
    uint32_t aK8   = (uint32_t)((lane >> 4) * 8);
    uint32_t wN    = (uint32_t)((lane >> 4) * 8 + (lane & 7));
    uint32_t wK8   = (uint32_t)(((lane >> 3) & 1) * 8);

    const int nph = HAS_A2 ? 2 : 1;
    for (int ph = 0; ph < nph; ph++) {
        const float* A = ph ? A2 : A1;
        int K = ph ? 128 : K1;
        uint32_t offh = ph ? offW2h : offW1h;
        uint32_t offl = ph ? offW2l : offW1l;
        if (ph) __syncthreads();             // all warps done reading A smem
        convA(A, K, MEAN && ph == 0);
        if (ph == 0) cp_wait_all();
        __syncthreads();

        auto ld_frags = [&](int ks, Frag& f) {
            uint32_t kb = (uint32_t)(ks * 16);
#pragma unroll
            for (int rt = 0; rt < 2; rt++) {
                uint32_t aoff = (((uint32_t)(rb * 32 + rt * 16) + aRowL) * WSTRIDE + kb + aK8) * 2;
                ldsm_x4(f.ah[rt], smBase + offAH + aoff);
                ldsm_x4(f.al[rt], smBase + offAL + aoff);
            }
#pragma unroll
            for (int tp = 0; tp < 4; tp++) {
                uint32_t woff = (((uint32_t)(cb * 64 + tp * 16) + wN) * WSTRIDE + kb + wK8) * 2;
                ldsm_x4(f.bh[tp], smBase + offh + woff);
                ldsm_x4(f.bl[tp], smBase + offl + woff);
            }
        };
        auto do_mmas = [&](const Frag& f) {
#pragma unroll
            for (int rt = 0; rt < 2; rt++) {
#pragma unroll
                for (int tp = 0; tp < 4; tp++) {
                    int t0 = rt * 8 + tp * 2;
                    mma_bf16(acc[t0],     f.ah[rt], f.bh[tp][0], f.bh[tp][1]);
                    mma_bf16(acc[t0],     f.ah[rt], f.bl[tp][0], f.bl[tp][1]);
                    mma_bf16(acc[t0],     f.al[rt], f.bh[tp][0], f.bh[tp][1]);
                    mma_bf16(acc[t0 + 1], f.ah[rt], f.bh[tp][2], f.bh[tp][3]);
                    mma_bf16(acc[t0 + 1], f.ah[rt], f.bl[tp][2], f.bl[tp][3]);
                    mma_bf16(acc[t0 + 1], f.al[rt], f.bh[tp][2], f.bh[tp][3]);
                }
            }
        };

        int ksteps = K >> 4;                 // 4 or 8 (always even)
        Frag f0, f1;
        ld_frags(0, f0);
#pragma unroll 1
        for (int ks = 0; ks < ksteps; ks += 2) {
            if (ks + 1 < ksteps) ld_frags(ks + 1, f1);
            do_mmas(f0);
            if (ks + 2 < ksteps) ld_frags(ks + 2, f0);
            if (ks + 1 < ksteps) do_mmas(f1);
        }
    }

    // epilogue: tile (rt, j): rows rb*32+rt*16+(lane>>2) (+8), col cb*64+j*8+(lane&3)*2
#pragma unroll
    for (int rt = 0; rt < 2; rt++) {
        int gr0 = row0 + rb * 32 + rt * 16 + (lane >> 2);
        int gr1 = gr0 + 8;
#pragma unroll
        for (int j = 0; j < 8; j++) {
            int col = cb * 64 + j * 8 + (lane & 3) * 2;
            float b0 = bias[col], b1 = bias[col + 1];
            float* a = acc[rt * 8 + j];
            float d0 = a[0] + b0, d1 = a[1] + b1;
            float d2 = a[2] + b0, d3 = a[3] + b1;
            if (RELU) {
                d0 = fmaxf(d0, 0.f); d1 = fmaxf(d1, 0.f);
                d2 = fmaxf(d2, 0.f); d3 = fmaxf(d3, 0.f);
            }
            if (gr0 < M) *reinterpret_cast<float2*>(out + (size_t)gr0 * 128 + col) = make_float2(d0, d1);
            if (gr1 < M) *reinterpret_cast<float2*>(out + (size_t)gr1 * 128 + col) = make_float2(d2, d3);
        }
    }
}

// ---------------- B-spline bases (uniform grid, grid_size=5, k=3 -> 8 bases) ----
__device__ __forceinline__ void bspline8(float x, float b[8]) {
    const float hstep = 2.0f / 5.0f;
    float g[12];
#pragma unroll
    for (int t = 0; t < 12; t++) g[t] = (float)(t - 3) * hstep - 1.0f;
    float p0[11], p1[10], p2[9];
#pragma unroll
    for (int t = 0; t < 11; t++) p0[t] = (x >= g[t] && x < g[t + 1]) ? 1.0f : 0.0f;
#pragma unroll
    for (int t = 0; t < 10; t++)
        p1[t] = ((x - g[t]) * (1.0f / (g[t + 1] - g[t]))) * p0[t]
              + ((g[t + 2] - x) * (1.0f / (g[t + 2] - g[t + 1]))) * p0[t + 1];
#pragma unroll
    for (int t = 0; t < 9; t++)
        p2[t] = ((x - g[t]) * (1.0f / (g[t + 2] - g[t]))) * p1[t]
              + ((g[t + 3] - x) * (1.0f / (g[t + 3] - g[t + 1]))) * p1[t + 1];
#pragma unroll
    for (int t = 0; t < 8; t++)
        b[t] = ((x - g[t]) * (1.0f / (g[t + 3] - g[t]))) * p2[t]
             + ((g[t + 4] - x) * (1.0f / (g[t + 4] - g[t + 1]))) * p2[t + 1];
}

__device__ __forceinline__ float silu(float x) {
    return x / (1.0f + __expf(-x));
}

// ---------------- KAN layer 1 (unchanged, known-good) -----------------------------
__global__ void __launch_bounds__(256)
kan1_kernel(const float* __restrict__ x,
            const float* __restrict__ spline,
            const float* __restrict__ scaler,
            const float* __restrict__ basew,
            float* __restrict__ out, int M)
{
    __shared__ __align__(16) float Bs[2][32][130];
    __shared__ __align__(16) float Ws[2][32][66];
    int tid = threadIdx.x;
    int ty = tid >> 4, tx = tid & 15;
    int row0 = blockIdx.x * 128;
    unsigned long long acc[4][4];
#pragma unroll
    for (int p = 0; p < 4; p++)
#pragma unroll
        for (int j = 0; j < 4; j++) acc[p][j] = 0ULL;

    auto fill_chunk = [&](int c, float nb[2][8], float nw[8]) {
        int f0 = c * 4;
#pragma unroll
        for (int it = 0; it < 2; it++) {
            int p = tid + it * 256;
            int feat = p & 3, r = p >> 2;
            int gr = row0 + r;
            float xv = (gr < M) ? x[(size_t)gr * 128 + f0 + feat] : 0.f;
            bspline8(xv, nb[it]);
        }
#pragma unroll
        for (int it = 0; it < 8; it++) {
            int idx = tid + it * 256;
            int kk = idx & 31, col = idx >> 5;
            nw[it] = spline[(size_t)col * 1024 + f0 * 8 + kk] * scaler[col * 128 + f0 + (kk >> 3)];
        }
    };
    auto sts_chunk = [&](const float nb[2][8], const float nw[8], int buf) {
#pragma unroll
        for (int it = 0; it < 2; it++) {
            int p = tid + it * 256;
            int feat = p & 3, r = p >> 2;
#pragma unroll
            for (int t = 0; t < 8; t++) Bs[buf][feat * 8 + t][r] = nb[it][t];
        }
#pragma unroll
        for (int it = 0; it < 8; it++) {
            int idx = tid + it * 256;
            Ws[buf][idx & 31][idx >> 5] = nw[it];
        }
    };

    {
        float nb[2][8], nw[8];
        fill_chunk(0, nb, nw);
        sts_chunk(nb, nw, 0);
    }
    __syncthreads();

    for (int c = 0; c < 32; c++) {
        int cur = c & 1;
        float nb[2][8], nw[8];
        if (c + 1 < 32) fill_chunk(c + 1, nb, nw);
#pragma unroll
        for (int kk = 0; kk < 32; kk++) {
            unsigned long long a2[4];
#pragma unroll
            for (int p = 0; p < 4; p++)
                a2[p] = *reinterpret_cast<const unsigned long long*>(&Bs[cur][kk][ty * 8 + 2 * p]);
            unsigned long long wd[4];
#pragma unroll
            for (int j = 0; j < 4; j++) wd[j] = dup_x2(Ws[cur][kk][tx + 16 * j]);
#pragma unroll
            for (int p = 0; p < 4; p++)
#pragma unroll
                for (int j = 0; j < 4; j++) fma_x2(acc[p][j], a2[p], wd[j]);
        }
        if (c + 1 < 32) sts_chunk(nb, nw, cur ^ 1);
        __syncthreads();
    }

    for (int f0 = 0; f0 < 128; f0 += 32) {
#pragma unroll
        for (int it = 0; it < 16; it++) {
            int p = tid + it * 256;
            int feat = p & 31, r = p >> 5;
            int gr = row0 + r;
            float xv = (gr < M) ? x[(size_t)gr * 128 + f0 + feat] : 0.f;
            Bs[0][feat][r] = silu(xv);
        }
#pragma unroll
        for (int it = 0; it < 8; it++) {
            int idx = tid + it * 256;
            int kk = idx & 31, col = idx >> 5;
            Ws[0][kk][col] = basew[(size_t)col * 128 + f0 + kk];
        }
        __syncthreads();
#pragma unroll
        for (int kk = 0; kk < 32; kk++) {
            unsigned long long a2[4];
#pragma unroll
            for (int p = 0; p < 4; p++)
                a2[p] = *reinterpret_cast<const unsigned long long*>(&Bs[0][kk][ty * 8 + 2 * p]);
            unsigned long long wd[4];
#pragma unroll
            for (int j = 0; j < 4; j++) wd[j] = dup_x2(Ws[0][kk][tx + 16 * j]);
#pragma unroll
            for (int p = 0; p < 4; p++)
#pragma unroll
                for (int j = 0; j < 4; j++) fma_x2(acc[p][j], a2[p], wd[j]);
        }
        __syncthreads();
    }

#pragma unroll
    for (int p = 0; p < 4; p++) {
        int gr0 = row0 + ty * 8 + 2 * p;
        int gr1 = gr0 + 1;
        float r0[4], r1[4];
#pragma unroll
        for (int j = 0; j < 4; j++) unpack_x2(acc[p][j], r0[j], r1[j]);
        if (gr0 < M) {
#pragma unroll
            for (int j = 0; j < 4; j++) out[(size_t)gr0 * 64 + tx + 16 * j] = r0[j];
        }
        if (gr1 < M) {
#pragma unroll
            for (int j = 0; j < 4; j++) out[(size_t)gr1 * 64 + tx + 16 * j] = r1[j];
        }
    }
}

// ---------------- KAN layer 2 (unchanged) ----------------------------------------
__global__ void kan2_kernel(const float* __restrict__ hin,
                            const float* __restrict__ spline,
                            const float* __restrict__ scaler,
                            const float* __restrict__ basew,
                            float* __restrict__ out, int M)
{
    __shared__ float sh[128][65];
    __shared__ float sw[2][64][8];
    __shared__ float sb[2][64];
    int tid = threadIdx.x;
    int row0 = blockIdx.x * 128;
    for (int idx = tid; idx < 1024; idx += 128) {
        int o = idx >> 9, rem = idx & 511, f = rem >> 3, t = rem & 7;
        sw[o][f][t] = spline[idx] * scaler[o * 64 + f];
    }
    if (tid < 128) sb[tid >> 6][tid & 63] = basew[tid];
    for (int idx = tid; idx < 128 * 64; idx += 128) {
        int r = idx >> 6, f = idx & 63;
        int gr = row0 + r;
        sh[r][f] = (gr < M) ? hin[(size_t)gr * 64 + f] : 0.f;
    }
    __syncthreads();
    int gr = row0 + tid;
    if (gr >= M) return;
    float acc0 = 0.f, acc1 = 0.f;
    for (int f = 0; f < 64; f++) {
        float xv = sh[tid][f];
        float s = silu(xv);
        acc0 += s * sb[0][f];
        acc1 += s * sb[1][f];
        float b[8];
        bspline8(xv, b);
#pragma unroll
        for (int t = 0; t < 8; t++) {
            acc0 += b[t] * sw[0][f][t];
            acc1 += b[t] * sw[1][f][t];
        }
    }
    out[(size_t)gr * 2 + 0] = acc0;
    out[(size_t)gr * 2 + 1] = acc1;
}

// ---------------- launch ----------------
extern "C" void kernel_launch(void* const* d_in, const int* in_sizes, int n_in,
                              void* d_out, int out_size)
{
    const float* x_email    = (const float*)d_in[0];
    const int*   ei_ue      = (const int*)d_in[1];
    const int*   ei_eu      = (const int*)d_in[2];
    const float* w_email    = (const float*)d_in[3];
    const float* b_email    = (const float*)d_in[4];
    const float* emb_user   = (const float*)d_in[5];
    const float* w_l1_ue_n  = (const float*)d_in[6];
    const float* b_l1_ue    = (const float*)d_in[7];
    const float* w_l1_ue_r  = (const float*)d_in[8];
    const float* w_l1_eu_n  = (const float*)d_in[9];
    const float* b_l1_eu    = (const float*)d_in[10];
    const float* w_l1_eu_r  = (const float*)d_in[11];
    const float* w_l2_ue_n  = (const float*)d_in[12];
    const float* b_l2_ue    = (const float*)d_in[13];
    const float* w_l2_ue_r  = (const float*)d_in[14];
    const float* kan1_base   = (const float*)d_in[18];
    const float* kan1_spline = (const float*)d_in[19];
    const float* kan1_scaler = (const float*)d_in[20];
    const float* kan2_base   = (const float*)d_in[22];
    const float* kan2_spline = (const float*)d_in[23];
    const float* kan2_scaler = (const float*)d_in[24];
    float* out = (float*)d_out;

    float *xe, *accE, *accE2, *e1, *accU, *u1, *hbuf, *cntE, *cntU;
    cudaGetSymbolAddress((void**)&xe,    g_xe);
    cudaGetSymbolAddress((void**)&accE,  g_accE);
    cudaGetSymbolAddress((void**)&accE2, g_accE2);
    cudaGetSymbolAddress((void**)&e1,    g_e1);
    cudaGetSymbolAddress((void**)&accU,  g_accU);
    cudaGetSymbolAddress((void**)&u1,    g_u1);
    cudaGetSymbolAddress((void**)&hbuf,  g_h);
    cudaGetSymbolAddress((void**)&cntE,  g_cntE);
    cudaGetSymbolAddress((void**)&cntU,  g_cntU);
    __nv_bfloat16 *weh, *wel, *wh, *wl;
    cudaGetSymbolAddress((void**)&weh, g_weh);
    cudaGetSymbolAddress((void**)&wel, g_wel);
    cudaGetSymbolAddress((void**)&wh,  g_wh);
    cudaGetSymbolAddress((void**)&wl,  g_wl);
    auto WH = [&](int m) { return wh + (size_t)m * 128 * WSTRIDE; };
    auto WL = [&](int m) { return wl + (size_t)m * 128 * WSTRIDE; };

    const int gE = (NE + 127) / 128;   // 1563
    const int gU = (NU + 127) / 128;   // 782
    const int gScat = (NEDGE / 8 * 32 + 255) / 256;  // 15625

    const int SMEM_1 = (int)(4 * TILEB);
    const int SMEM_2 = (int)(6 * TILEB);
    cudaFuncSetAttribute(gemm_tc<false, false, false>,
                         cudaFuncAttributeMaxDynamicSharedMemorySize, SMEM_1);
    cudaFuncSetAttribute(gemm_tc<true, true, true>,
                         cudaFuncAttributeMaxDynamicSharedMemorySize, SMEM_2);

    init_kernel<<<4096, 256>>>(w_email, w_l1_ue_n, w_l1_ue_r,
                               w_l1_eu_n, w_l1_eu_r, w_l2_ue_n, w_l2_ue_r);
    gemm_tc<false, false, false><<<gE, 256, SMEM_1>>>(
        x_email, 64, weh, wel, nullptr, nullptr, nullptr, b_email, nullptr, xe, NE);
    scatter_kernel<<<gScat, 256>>>(ei_ue, ei_ue + NEDGE, emb_user, accE, cntE, 1);
    gemm_tc<true, true, true><<<gE, 256, SMEM_2>>>(
        accE, 128, WH(0), WL(0), xe, WH(1), WL(1), b_l1_ue, cntE, e1, NE);
    scatter_kernel<<<gScat, 256>>>(ei_eu, ei_eu + NEDGE, xe, accU, cntU, 1);
    gemm_tc<true, true, true><<<gU, 256, SMEM_2>>>(
        accU, 128, WH(2), WL(2), emb_user, WH(3), WL(3), b_l1_eu, cntU, u1, NU);
    scatter_kernel<<<gScat, 256>>>(ei_ue, ei_ue + NEDGE, u1, accE2, nullptr, 0);
    gemm_tc<true, true, true><<<gE, 256, SMEM_2>>>(
        accE2, 128, WH(4), WL(4), e1, WH(5), WL(5), b_l2_ue, cntE, xe, NE);
    kan1_kernel<<<gE, 256>>>(xe, kan1_spline, kan1_scaler, kan1_base, hbuf, NE);
    kan2_kernel<<<gE, 128>>>(hbuf, kan2_spline, kan2_scaler, kan2_base, out, NE);
}

// round 14
// speedup vs baseline: 1.0283x; 1.0283x over previous
#include <cuda_runtime.h>
#include <cuda_bf16.h>
#include <math.h>
#include <stdint.h>

#define NE 200000
#define NU 100000
#define NEDGE 1000000
#define HDIM 128

// ---------------- scratch (static device arrays; no allocation) ----------------
__device__ float g_xe[(size_t)NE * HDIM];
__device__ float g_accE[(size_t)NE * HDIM];
__device__ float g_accE2[(size_t)NE * HDIM];
__device__ float g_e1[(size_t)NE * HDIM];
__device__ float g_accU[(size_t)NU * HDIM];
__device__ float g_u1[(size_t)NU * HDIM];
__device__ float g_h[(size_t)NE * 64];
__device__ float g_cntE[NE];
__device__ float g_cntU[NU];
// bf16 hi/lo weight tiles, padded row stride 136 (272B -> conflict-free ldmatrix)
#define WSTRIDE 136
__device__ __align__(16) __nv_bfloat16 g_weh[128 * WSTRIDE];
__device__ __align__(16) __nv_bfloat16 g_wel[128 * WSTRIDE];
__device__ __align__(16) __nv_bfloat16 g_wh[6][128 * WSTRIDE];
__device__ __align__(16) __nv_bfloat16 g_wl[6][128 * WSTRIDE];

// ---------------- helpers ----------------
__device__ __forceinline__ void fma_x2(unsigned long long& acc, unsigned long long a,
                                       unsigned long long b) {
    asm("fma.rn.f32x2 %0, %1, %2, %0;" : "+l"(acc) : "l"(a), "l"(b));
}
__device__ __forceinline__ unsigned long long dup_x2(float v) {
    unsigned long long r;
    asm("mov.b64 %0, {%1, %1};" : "=l"(r) : "f"(v));
    return r;
}
__device__ __forceinline__ void unpack_x2(unsigned long long v, float& lo, float& hi) {
    asm("mov.b64 {%0, %1}, %2;" : "=f"(lo), "=f"(hi) : "l"(v));
}
__device__ __forceinline__ uint32_t smem_u32(const void* p) {
    return (uint32_t)__cvta_generic_to_shared(p);
}
__device__ __forceinline__ void cp_async16(uint32_t dst, const void* src) {
    asm volatile("cp.async.ca.shared.global [%0], [%1], 16;" :: "r"(dst), "l"(src));
}
__device__ __forceinline__ void cp_commit() { asm volatile("cp.async.commit_group;"); }
__device__ __forceinline__ void cp_wait_all() {
    asm volatile("cp.async.wait_group 0;" ::: "memory");
}
__device__ __forceinline__ uint32_t pack_bf16(__nv_bfloat16 a, __nv_bfloat16 b) {
    uint16_t ua = *(uint16_t*)&a, ub = *(uint16_t*)&b;
    return (uint32_t)ua | ((uint32_t)ub << 16);
}
__device__ __forceinline__ void ldsm_x4(uint32_t r[4], uint32_t addr) {
    asm volatile("ldmatrix.sync.aligned.m8n8.x4.shared.b16 {%0,%1,%2,%3}, [%4];"
                 : "=r"(r[0]), "=r"(r[1]), "=r"(r[2]), "=r"(r[3]) : "r"(addr));
}
__device__ __forceinline__ void mma_bf16(float d[4], const uint32_t a[4],
                                         uint32_t b0, uint32_t b1) {
    asm volatile(
        "mma.sync.aligned.m16n8k16.row.col.f32.bf16.bf16.f32 "
        "{%0,%1,%2,%3}, {%4,%5,%6,%7}, {%8,%9}, {%0,%1,%2,%3};"
        : "+f"(d[0]), "+f"(d[1]), "+f"(d[2]), "+f"(d[3])
        : "r"(a[0]), "r"(a[1]), "r"(a[2]), "r"(a[3]), "r"(b0), "r"(b1));
}

// ---------------- init: zero accumulators + split weights to bf16 hi/lo ----------
__global__ void init_kernel(const float* we, const float* w1n, const float* w1r,
                            const float* w2n, const float* w2r,
                            const float* w3n, const float* w3r)
{
    int i = blockIdx.x * blockDim.x + threadIdx.x;
    int stride = gridDim.x * blockDim.x;
    const int nE4 = NE * HDIM / 4, nU4 = NU * HDIM / 4;
    const int cE4 = NE / 4, cU4 = NU / 4;
    float4 z = make_float4(0.f, 0.f, 0.f, 0.f);
    float4* aE  = (float4*)g_accE;
    float4* aE2 = (float4*)g_accE2;
    float4* aU  = (float4*)g_accU;
    for (int k = i; k < nE4; k += stride) { aE[k] = z; aE2[k] = z; }
    for (int k = i; k < nU4; k += stride) aU[k] = z;
    for (int k = i; k < cE4; k += stride) ((float4*)g_cntE)[k] = z;
    for (int k = i; k < cU4; k += stride) ((float4*)g_cntU)[k] = z;
    for (int k = i; k < 128 * 64; k += stride) {
        int n = k >> 6, c = k & 63;
        float w = we[n * 64 + c];
        __nv_bfloat16 h = __float2bfloat16(w);
        __nv_bfloat16 l = __float2bfloat16(w - __bfloat162float(h));
        g_weh[n * WSTRIDE + c] = h;
        g_wel[n * WSTRIDE + c] = l;
    }
    for (int k = i; k < 6 * 128 * 128; k += stride) {
        int m = k >> 14, r = k & 16383;
        int n = r >> 7, c = r & 127;
        const float* src;
        switch (m) {
            case 0: src = w1n; break;
            case 1: src = w1r; break;
            case 2: src = w2n; break;
            case 3: src = w2r; break;
            case 4: src = w3n; break;
            default: src = w3r; break;
        }
        float w = src[n * 128 + c];
        __nv_bfloat16 h = __float2bfloat16(w);
        __nv_bfloat16 l = __float2bfloat16(w - __bfloat162float(h));
        g_wh[m][n * WSTRIDE + c] = h;
        g_wl[m][n * WSTRIDE + c] = l;
    }
}

// ---------------- edge scatter: one warp per 8 edges (MLP=8), vector RED --------
__global__ void scatter_kernel(const int* __restrict__ src, const int* __restrict__ dst,
                               const float* __restrict__ xsrc,
                               float* __restrict__ accum, float* __restrict__ cnt,
                               int doCnt)
{
    int warp = (blockIdx.x * blockDim.x + threadIdx.x) >> 5;
    int lane = threadIdx.x & 31;
    int e0 = warp * 8;
    if (e0 >= NEDGE) return;
    int4 sa = *reinterpret_cast<const int4*>(src + e0);
    int4 sb = *reinterpret_cast<const int4*>(src + e0 + 4);
    int4 da = *reinterpret_cast<const int4*>(dst + e0);
    int4 db = *reinterpret_cast<const int4*>(dst + e0 + 4);
    int s[8] = {sa.x, sa.y, sa.z, sa.w, sb.x, sb.y, sb.z, sb.w};
    int d[8] = {da.x, da.y, da.z, da.w, db.x, db.y, db.z, db.w};
    float4 v[8];
#pragma unroll
    for (int i = 0; i < 8; i++)
        v[i] = *reinterpret_cast<const float4*>(xsrc + (size_t)s[i] * HDIM + lane * 4);
#pragma unroll
    for (int i = 0; i < 8; i++) {
        float* a = accum + (size_t)d[i] * HDIM + lane * 4;
        asm volatile("red.global.add.v4.f32 [%0], {%1, %2, %3, %4};"
                     :: "l"(a), "f"(v[i].x), "f"(v[i].y), "f"(v[i].z), "f"(v[i].w) : "memory");
    }
    if (doCnt && lane == 0) {
#pragma unroll
        for (int i = 0; i < 8; i++) {
            float one = 1.0f;
            asm volatile("red.global.add.f32 [%0], %1;" :: "l"(cnt + d[i]), "f"(one) : "memory");
        }
    }
}

// ---------------- tensor-core combine GEMM: 128 rows x 64 cols per CTA ----------
// grid.x = 2 * rowTiles; rowTile = bid>>1, colHalf = bid&1.
// smem: A hi/lo (2x34816) + W hi/lo one phase (2x17408) = 104448 -> 2 CTAs/SM.
// W2 reloaded into same buffers between phases (overlapped with A2 conversion).
// 8 warps: warp w: rows (w>>1)*32..+31, cols (w&1)*32..+31 within the 64-col half.
#define ATILE 34816u
#define WTILE 17408u
template<bool HAS_A2, bool RELU, bool MEAN>
__global__ void __launch_bounds__(256, 2)
gemm_tc(const float* __restrict__ A1, int K1,
        const __nv_bfloat16* __restrict__ W1h, const __nv_bfloat16* __restrict__ W1l,
        const float* __restrict__ A2,
        const __nv_bfloat16* __restrict__ W2h, const __nv_bfloat16* __restrict__ W2l,
        const float* __restrict__ bias, const float* __restrict__ cnt,
        float* __restrict__ out, int M)
{
    extern __shared__ char dsm[];
    uint32_t smBase = smem_u32(dsm);
    const uint32_t offAH = 0, offAL = ATILE;
    const uint32_t offWh = 2 * ATILE, offWl = 2 * ATILE + WTILE;

    int tid = threadIdx.x;
    int widx = tid >> 5, lane = tid & 31;
    int rb = widx >> 1;          // row block 0..3 (32 rows)
    int cw = widx & 1;           // col sub-block 0..1 (32 cols)
    int ch = blockIdx.x & 1;     // which 64-col half of the output
    int row0 = (blockIdx.x >> 1) * 128;

    // W gmem base for this col half (64 n-rows)
    const char* w1hp = (const char*)(W1h + ch * 64 * WSTRIDE);
    const char* w1lp = (const char*)(W1l + ch * 64 * WSTRIDE);

    auto cp_w = [&](const char* hsrc, const char* lsrc) {
        for (uint32_t i = tid * 16; i < WTILE; i += 256 * 16) {
            cp_async16(smBase + offWh + i, hsrc + i);
            cp_async16(smBase + offWl + i, lsrc + i);
        }
        cp_commit();
    };
    cp_w(w1hp, w1lp);

    // A fp32 -> (hi,lo) bf16 conversion into smem tiles; 1/cnt folded if mean
    auto convA = [&](const float* A, int K, bool mean) {
        int r = tid >> 1;
        int half = tid & 1;
        int cwid = K >> 1;
        int c0 = half * cwid;
        int gr = row0 + r;
        float inv = 1.f;
        if (mean) {
            float cv = (gr < M) ? cnt[gr] : 1.f;
            inv = 1.f / fmaxf(cv, 1.f);
        }
        const float* Arow = A + (size_t)gr * K;
        char* pH = dsm + offAH + (uint32_t)r * 272u;
        char* pL = dsm + offAL + (uint32_t)r * 272u;
        for (int c = c0; c < c0 + cwid; c += 4) {
            float4 a = make_float4(0.f, 0.f, 0.f, 0.f);
            if (gr < M) a = *reinterpret_cast<const float4*>(Arow + c);
            float v0 = a.x * inv, v1 = a.y * inv, v2 = a.z * inv, v3 = a.w * inv;
            __nv_bfloat16 h0 = __float2bfloat16(v0), h1 = __float2bfloat16(v1);
            __nv_bfloat16 h2 = __float2bfloat16(v2), h3 = __float2bfloat16(v3);
            __nv_bfloat16 l0 = __float2bfloat16(v0 - __bfloat162float(h0));
            __nv_bfloat16 l1 = __float2bfloat16(v1 - __bfloat162float(h1));
            __nv_bfloat16 l2 = __float2bfloat16(v2 - __bfloat162float(h2));
            __nv_bfloat16 l3 = __float2bfloat16(v3 - __bfloat162float(h3));
            *(uint32_t*)(pH + c * 2)     = pack_bf16(h0, h1);
            *(uint32_t*)(pH + c * 2 + 4) = pack_bf16(h2, h3);
            *(uint32_t*)(pL + c * 2)     = pack_bf16(l0, l1);
            *(uint32_t*)(pL + c * 2 + 4) = pack_bf16(l2, l3);
        }
    };

    // acc tile index: rt*4 + tp*2 + j  (rt row-16 0..1, tp col-16 0..1, j n8 0..1)
    float acc[8][4];
#pragma unroll
    for (int t = 0; t < 8; t++)
#pragma unroll
        for (int q = 0; q < 4; q++) acc[t][q] = 0.f;

    // per-lane ldmatrix address components
    uint32_t aRowL = (uint32_t)(lane & 15);
    uint32_t aK8   = (uint32_t)((lane >> 4) * 8);
    uint32_t wN    = (uint32_t)((lane >> 4) * 8 + (lane & 7));
    uint32_t wK8   = (uint32_t)(((lane >> 3) & 1) * 8);

    auto mma_phase = [&](int K) {
        int ksteps = K >> 4;
#pragma unroll 1
        for (int ks = 0; ks < ksteps; ks++) {
            uint32_t kb = (uint32_t)(ks * 16);
            uint32_t ah[2][4], al[2][4];
#pragma unroll
            for (int rt = 0; rt < 2; rt++) {
                uint32_t aoff = (((uint32_t)(rb * 32 + rt * 16) + aRowL) * WSTRIDE + kb + aK8) * 2;
                ldsm_x4(ah[rt], smBase + offAH + aoff);
                ldsm_x4(al[rt], smBase + offAL + aoff);
            }
            uint32_t bh[2][4], bl[2][4];
#pragma unroll
            for (int tp = 0; tp < 2; tp++) {
                uint32_t woff = (((uint32_t)(cw * 32 + tp * 16) + wN) * WSTRIDE + kb + wK8) * 2;
                ldsm_x4(bh[tp], smBase + offWh + woff);
                ldsm_x4(bl[tp], smBase + offWl + woff);
            }
#pragma unroll
            for (int rt = 0; rt < 2; rt++) {
#pragma unroll
                for (int tp = 0; tp < 2; tp++) {
                    int t0 = rt * 4 + tp * 2;
                    mma_bf16(acc[t0],     ah[rt], bh[tp][0], bh[tp][1]);
                    mma_bf16(acc[t0],     ah[rt], bl[tp][0], bl[tp][1]);
                    mma_bf16(acc[t0],     al[rt], bh[tp][0], bh[tp][1]);
                    mma_bf16(acc[t0 + 1], ah[rt], bh[tp][2], bh[tp][3]);
                    mma_bf16(acc[t0 + 1], ah[rt], bl[tp][2], bl[tp][3]);
                    mma_bf16(acc[t0 + 1], al[rt], bh[tp][2], bh[tp][3]);
                }
            }
        }
    };

    // phase 0
    convA(A1, K1, MEAN);
    cp_wait_all();
    __syncthreads();
    mma_phase(K1);

    if (HAS_A2) {
        __syncthreads();   // all warps done reading A and W smem
        cp_w((const char*)(W2h + ch * 64 * WSTRIDE), (const char*)(W2l + ch * 64 * WSTRIDE));
        convA(A2, 128, false);
        cp_wait_all();
        __syncthreads();
        mma_phase(128);
    }

    // epilogue: tile (rt,tp,j): rows rb*32+rt*16+(lane>>2) (+8),
    //           col ch*64 + cw*32 + (tp*2+j)*8 + (lane&3)*2
#pragma unroll
    for (int rt = 0; rt < 2; rt++) {
        int gr0 = row0 + rb * 32 + rt * 16 + (lane >> 2);
        int gr1 = gr0 + 8;
#pragma unroll
        for (int tp = 0; tp < 2; tp++) {
#pragma unroll
            for (int j = 0; j < 2; j++) {
                int col = ch * 64 + cw * 32 + (tp * 2 + j) * 8 + (lane & 3) * 2;
                float b0 = bias[col], b1 = bias[col + 1];
                float* a = acc[rt * 4 + tp * 2 + j];
                float d0 = a[0] + b0, d1 = a[1] + b1;
                float d2 = a[2] + b0, d3 = a[3] + b1;
                if (RELU) {
                    d0 = fmaxf(d0, 0.f); d1 = fmaxf(d1, 0.f);
                    d2 = fmaxf(d2, 0.f); d3 = fmaxf(d3, 0.f);
                }
                if (gr0 < M) *reinterpret_cast<float2*>(out + (size_t)gr0 * 128 + col) = make_float2(d0, d1);
                if (gr1 < M) *reinterpret_cast<float2*>(out + (size_t)gr1 * 128 + col) = make_float2(d2, d3);
            }
        }
    }
}

// ---------------- B-spline bases (uniform grid, grid_size=5, k=3 -> 8 bases) ----
__device__ __forceinline__ void bspline8(float x, float b[8]) {
    const float hstep = 2.0f / 5.0f;
    float g[12];
#pragma unroll
    for (int t = 0; t < 12; t++) g[t] = (float)(t - 3) * hstep - 1.0f;
    float p0[11], p1[10], p2[9];
#pragma unroll
    for (int t = 0; t < 11; t++) p0[t] = (x >= g[t] && x < g[t + 1]) ? 1.0f : 0.0f;
#pragma unroll
    for (int t = 0; t < 10; t++)
        p1[t] = ((x - g[t]) * (1.0f / (g[t + 1] - g[t]))) * p0[t]
              + ((g[t + 2] - x) * (1.0f / (g[t + 2] - g[t + 1]))) * p0[t + 1];
#pragma unroll
    for (int t = 0; t < 9; t++)
        p2[t] = ((x - g[t]) * (1.0f / (g[t + 2] - g[t]))) * p1[t]
              + ((g[t + 3] - x) * (1.0f / (g[t + 3] - g[t + 1]))) * p1[t + 1];
#pragma unroll
    for (int t = 0; t < 8; t++)
        b[t] = ((x - g[t]) * (1.0f / (g[t + 3] - g[t]))) * p2[t]
             + ((g[t + 4] - x) * (1.0f / (g[t + 4] - g[t + 1]))) * p2[t + 1];
}

__device__ __forceinline__ float silu(float x) {
    return x / (1.0f + __expf(-x));
}

// ---------------- KAN layer 1 (unchanged, known-good) -----------------------------
__global__ void __launch_bounds__(256)
kan1_kernel(const float* __restrict__ x,
            const float* __restrict__ spline,
            const float* __restrict__ scaler,
            const float* __restrict__ basew,
            float* __restrict__ out, int M)
{
    __shared__ __align__(16) float Bs[2][32][130];
    __shared__ __align__(16) float Ws[2][32][66];
    int tid = threadIdx.x;
    int ty = tid >> 4, tx = tid & 15;
    int row0 = blockIdx.x * 128;
    unsigned long long acc[4][4];
#pragma unroll
    for (int p = 0; p < 4; p++)
#pragma unroll
        for (int j = 0; j < 4; j++) acc[p][j] = 0ULL;

    auto fill_chunk = [&](int c, float nb[2][8], float nw[8]) {
        int f0 = c * 4;
#pragma unroll
        for (int it = 0; it < 2; it++) {
            int p = tid + it * 256;
            int feat = p & 3, r = p >> 2;
            int gr = row0 + r;
            float xv = (gr < M) ? x[(size_t)gr * 128 + f0 + feat] : 0.f;
            bspline8(xv, nb[it]);
        }
#pragma unroll
        for (int it = 0; it < 8; it++) {
            int idx = tid + it * 256;
            int kk = idx & 31, col = idx >> 5;
            nw[it] = spline[(size_t)col * 1024 + f0 * 8 + kk] * scaler[col * 128 + f0 + (kk >> 3)];
        }
    };
    auto sts_chunk = [&](const float nb[2][8], const float nw[8], int buf) {
#pragma unroll
        for (int it = 0; it < 2; it++) {
            int p = tid + it * 256;
            int feat = p & 3, r = p >> 2;
#pragma unroll
            for (int t = 0; t < 8; t++) Bs[buf][feat * 8 + t][r] = nb[it][t];
        }
#pragma unroll
        for (int it = 0; it < 8; it++) {
            int idx = tid + it * 256;
            Ws[buf][idx & 31][idx >> 5] = nw[it];
        }
    };

    {
        float nb[2][8], nw[8];
        fill_chunk(0, nb, nw);
        sts_chunk(nb, nw, 0);
    }
    __syncthreads();

    for (int c = 0; c < 32; c++) {
        int cur = c & 1;
        float nb[2][8], nw[8];
        if (c + 1 < 32) fill_chunk(c + 1, nb, nw);
#pragma unroll
        for (int kk = 0; kk < 32; kk++) {
            unsigned long long a2[4];
#pragma unroll
            for (int p = 0; p < 4; p++)
                a2[p] = *reinterpret_cast<const unsigned long long*>(&Bs[cur][kk][ty * 8 + 2 * p]);
            unsigned long long wd[4];
#pragma unroll
            for (int j = 0; j < 4; j++) wd[j] = dup_x2(Ws[cur][kk][tx + 16 * j]);
#pragma unroll
            for (int p = 0; p < 4; p++)
#pragma unroll
                for (int j = 0; j < 4; j++) fma_x2(acc[p][j], a2[p], wd[j]);
        }
        if (c + 1 < 32) sts_chunk(nb, nw, cur ^ 1);
        __syncthreads();
    }

    for (int f0 = 0; f0 < 128; f0 += 32) {
#pragma unroll
        for (int it = 0; it < 16; it++) {
            int p = tid + it * 256;
            int feat = p & 31, r = p >> 5;
            int gr = row0 + r;
            float xv = (gr < M) ? x[(size_t)gr * 128 + f0 + feat] : 0.f;
            Bs[0][feat][r] = silu(xv);
        }
#pragma unroll
        for (int it = 0; it < 8; it++) {
            int idx = tid + it * 256;
            int kk = idx & 31, col = idx >> 5;
            Ws[0][kk][col] = basew[(size_t)col * 128 + f0 + kk];
        }
        __syncthreads();
#pragma unroll
        for (int kk = 0; kk < 32; kk++) {
            unsigned long long a2[4];
#pragma unroll
            for (int p = 0; p < 4; p++)
                a2[p] = *reinterpret_cast<const unsigned long long*>(&Bs[0][kk][ty * 8 + 2 * p]);
            unsigned long long wd[4];
#pragma unroll
            for (int j = 0; j < 4; j++) wd[j] = dup_x2(Ws[0][kk][tx + 16 * j]);
#pragma unroll
            for (int p = 0; p < 4; p++)
#pragma unroll
                for (int j = 0; j < 4; j++) fma_x2(acc[p][j], a2[p], wd[j]);
        }
        __syncthreads();
    }

#pragma unroll
    for (int p = 0; p < 4; p++) {
        int gr0 = row0 + ty * 8 + 2 * p;
        int gr1 = gr0 + 1;
        float r0[4], r1[4];
#pragma unroll
        for (int j = 0; j < 4; j++) unpack_x2(acc[p][j], r0[j], r1[j]);
        if (gr0 < M) {
#pragma unroll
            for (int j = 0; j < 4; j++) out[(size_t)gr0 * 64 + tx + 16 * j] = r0[j];
        }
        if (gr1 < M) {
#pragma unroll
            for (int j = 0; j < 4; j++) out[(size_t)gr1 * 64 + tx + 16 * j] = r1[j];
        }
    }
}

// ---------------- KAN layer 2 (unchanged) ----------------------------------------
__global__ void kan2_kernel(const float* __restrict__ hin,
                            const float* __restrict__ spline,
                            const float* __restrict__ scaler,
                            const float* __restrict__ basew,
                            float* __restrict__ out, int M)
{
    __shared__ float sh[128][65];
    __shared__ float sw[2][64][8];
    __shared__ float sb[2][64];
    int tid = threadIdx.x;
    int row0 = blockIdx.x * 128;
    for (int idx = tid; idx < 1024; idx += 128) {
        int o = idx >> 9, rem = idx & 511, f = rem >> 3, t = rem & 7;
        sw[o][f][t] = spline[idx] * scaler[o * 64 + f];
    }
    if (tid < 128) sb[tid >> 6][tid & 63] = basew[tid];
    for (int idx = tid; idx < 128 * 64; idx += 128) {
        int r = idx >> 6, f = idx & 63;
        int gr = row0 + r;
        sh[r][f] = (gr < M) ? hin[(size_t)gr * 64 + f] : 0.f;
    }
    __syncthreads();
    int gr = row0 + tid;
    if (gr >= M) return;
    float acc0 = 0.f, acc1 = 0.f;
    for (int f = 0; f < 64; f++) {
        float xv = sh[tid][f];
        float s = silu(xv);
        acc0 += s * sb[0][f];
        acc1 += s * sb[1][f];
        float b[8];
        bspline8(xv, b);
#pragma unroll
        for (int t = 0; t < 8; t++) {
            acc0 += b[t] * sw[0][f][t];
            acc1 += b[t] * sw[1][f][t];
        }
    }
    out[(size_t)gr * 2 + 0] = acc0;
    out[(size_t)gr * 2 + 1] = acc1;
}

// ---------------- launch ----------------
extern "C" void kernel_launch(void* const* d_in, const int* in_sizes, int n_in,
                              void* d_out, int out_size)
{
    const float* x_email    = (const float*)d_in[0];
    const int*   ei_ue      = (const int*)d_in[1];
    const int*   ei_eu      = (const int*)d_in[2];
    const float* w_email    = (const float*)d_in[3];
    const float* b_email    = (const float*)d_in[4];
    const float* emb_user   = (const float*)d_in[5];
    const float* w_l1_ue_n  = (const float*)d_in[6];
    const float* b_l1_ue    = (const float*)d_in[7];
    const float* w_l1_ue_r  = (const float*)d_in[8];
    const float* w_l1_eu_n  = (const float*)d_in[9];
    const float* b_l1_eu    = (const float*)d_in[10];
    const float* w_l1_eu_r  = (const float*)d_in[11];
    const float* w_l2_ue_n  = (const float*)d_in[12];
    const float* b_l2_ue    = (const float*)d_in[13];
    const float* w_l2_ue_r  = (const float*)d_in[14];
    const float* kan1_base   = (const float*)d_in[18];
    const float* kan1_spline = (const float*)d_in[19];
    const float* kan1_scaler = (const float*)d_in[20];
    const float* kan2_base   = (const float*)d_in[22];
    const float* kan2_spline = (const float*)d_in[23];
    const float* kan2_scaler = (const float*)d_in[24];
    float* out = (float*)d_out;

    float *xe, *accE, *accE2, *e1, *accU, *u1, *hbuf, *cntE, *cntU;
    cudaGetSymbolAddress((void**)&xe,    g_xe);
    cudaGetSymbolAddress((void**)&accE,  g_accE);
    cudaGetSymbolAddress((void**)&accE2, g_accE2);
    cudaGetSymbolAddress((void**)&e1,    g_e1);
    cudaGetSymbolAddress((void**)&accU,  g_accU);
    cudaGetSymbolAddress((void**)&u1,    g_u1);
    cudaGetSymbolAddress((void**)&hbuf,  g_h);
    cudaGetSymbolAddress((void**)&cntE,  g_cntE);
    cudaGetSymbolAddress((void**)&cntU,  g_cntU);
    __nv_bfloat16 *weh, *wel, *wh, *wl;
    cudaGetSymbolAddress((void**)&weh, g_weh);
    cudaGetSymbolAddress((void**)&wel, g_wel);
    cudaGetSymbolAddress((void**)&wh,  g_wh);
    cudaGetSymbolAddress((void**)&wl,  g_wl);
    auto WH = [&](int m) { return wh + (size_t)m * 128 * WSTRIDE; };
    auto WL = [&](int m) { return wl + (size_t)m * 128 * WSTRIDE; };

    const int gE = (NE + 127) / 128;   // 1563
    const int gU = (NU + 127) / 128;   // 782
    const int gScat = (NEDGE / 8 * 32 + 255) / 256;  // 15625

    const int SMEM_TC = (int)(2 * ATILE + 2 * WTILE);   // 104448
    cudaFuncSetAttribute(gemm_tc<false, false, false>,
                         cudaFuncAttributeMaxDynamicSharedMemorySize, SMEM_TC);
    cudaFuncSetAttribute(gemm_tc<true, true, true>,
                         cudaFuncAttributeMaxDynamicSharedMemorySize, SMEM_TC);

    init_kernel<<<4096, 256>>>(w_email, w_l1_ue_n, w_l1_ue_r,
                               w_l1_eu_n, w_l1_eu_r, w_l2_ue_n, w_l2_ue_r);
    gemm_tc<false, false, false><<<gE * 2, 256, SMEM_TC>>>(
        x_email, 64, weh, wel, nullptr, nullptr, nullptr, b_email, nullptr, xe, NE);
    scatter_kernel<<<gScat, 256>>>(ei_ue, ei_ue + NEDGE, emb_user, accE, cntE, 1);
    gemm_tc<true, true, true><<<gE * 2, 256, SMEM_TC>>>(
        accE, 128, WH(0), WL(0), xe, WH(1), WL(1), b_l1_ue, cntE, e1, NE);
    scatter_kernel<<<gScat, 256>>>(ei_eu, ei_eu + NEDGE, xe, accU, cntU, 1);
    gemm_tc<true, true, true><<<gU * 2, 256, SMEM_TC>>>(
        accU, 128, WH(2), WL(2), emb_user, WH(3), WL(3), b_l1_eu, cntU, u1, NU);
    scatter_kernel<<<gScat, 256>>>(ei_ue, ei_ue + NEDGE, u1, accE2, nullptr, 0);
    gemm_tc<true, true, true><<<gE * 2, 256, SMEM_TC>>>(
        accE2, 128, WH(4), WL(4), e1, WH(5), WL(5), b_l2_ue, cntE, xe, NE);
    kan1_kernel<<<gE, 256>>>(xe, kan1_spline, kan1_scaler, kan1_base, hbuf, NE);
    kan2_kernel<<<gE, 128>>>(hbuf, kan2_spline, kan2_scaler, kan2_base, out, NE);
}

// round 15
// speedup vs baseline: 1.1056x; 1.0751x over previous
#include <cuda_runtime.h>
#include <cuda_bf16.h>
#include <math.h>
#include <stdint.h>

#define NE 200000
#define NU 100000
#define NEDGE 1000000
#define HDIM 128

// ---------------- scratch (static device arrays; no allocation) ----------------
__device__ float g_xe[(size_t)NE * HDIM];     // e2 lives here
__device__ float g_accE[(size_t)NE * HDIM];
__device__ float g_accE2[(size_t)NE * HDIM];
__device__ float g_e1[(size_t)NE * HDIM];
__device__ float g_accUx[(size_t)NU * 64];    // x_email aggregated (64-dim)
__device__ float g_u1[(size_t)NU * HDIM];
__device__ float g_h[(size_t)NE * 64];
__device__ float g_cntE[NE];
__device__ float g_cntU[NU];
__device__ float g_bias1[128];                // b_l1_ue + W1r@b_email
__device__ float g_gb2[128];                  // W2n@b_email (gated by cntU>0)
// bf16 hi/lo weight tiles, padded row stride 136 (272B -> conflict-free ldmatrix)
#define WSTRIDE 136
__device__ __align__(16) __nv_bfloat16 g_wh[6][128 * WSTRIDE];
__device__ __align__(16) __nv_bfloat16 g_wl[6][128 * WSTRIDE];
__device__ __align__(16) __nv_bfloat16 g_wch[2][128 * WSTRIDE];  // composites (K=64)
__device__ __align__(16) __nv_bfloat16 g_wcl[2][128 * WSTRIDE];

// ---------------- helpers ----------------
__device__ __forceinline__ void fma_x2(unsigned long long& acc, unsigned long long a,
                                       unsigned long long b) {
    asm("fma.rn.f32x2 %0, %1, %2, %0;" : "+l"(acc) : "l"(a), "l"(b));
}
__device__ __forceinline__ unsigned long long dup_x2(float v) {
    unsigned long long r;
    asm("mov.b64 %0, {%1, %1};" : "=l"(r) : "f"(v));
    return r;
}
__device__ __forceinline__ void unpack_x2(unsigned long long v, float& lo, float& hi) {
    asm("mov.b64 {%0, %1}, %2;" : "=f"(lo), "=f"(hi) : "l"(v));
}
__device__ __forceinline__ uint32_t smem_u32(const void* p) {
    return (uint32_t)__cvta_generic_to_shared(p);
}
__device__ __forceinline__ void cp_async16(uint32_t dst, const void* src) {
    asm volatile("cp.async.ca.shared.global [%0], [%1], 16;" :: "r"(dst), "l"(src));
}
__device__ __forceinline__ void cp_commit() { asm volatile("cp.async.commit_group;"); }
__device__ __forceinline__ void cp_wait_all() {
    asm volatile("cp.async.wait_group 0;" ::: "memory");
}
__device__ __forceinline__ uint32_t pack_bf16(__nv_bfloat16 a, __nv_bfloat16 b) {
    uint16_t ua = *(uint16_t*)&a, ub = *(uint16_t*)&b;
    return (uint32_t)ua | ((uint32_t)ub << 16);
}
__device__ __forceinline__ void ldsm_x4(uint32_t r[4], uint32_t addr) {
    asm volatile("ldmatrix.sync.aligned.m8n8.x4.shared.b16 {%0,%1,%2,%3}, [%4];"
                 : "=r"(r[0]), "=r"(r[1]), "=r"(r[2]), "=r"(r[3]) : "r"(addr));
}
__device__ __forceinline__ void mma_bf16(float d[4], const uint32_t a[4],
                                         uint32_t b0, uint32_t b1) {
    asm volatile(
        "mma.sync.aligned.m16n8k16.row.col.f32.bf16.bf16.f32 "
        "{%0,%1,%2,%3}, {%4,%5,%6,%7}, {%8,%9}, {%0,%1,%2,%3};"
        : "+f"(d[0]), "+f"(d[1]), "+f"(d[2]), "+f"(d[3])
        : "r"(a[0]), "r"(a[1]), "r"(a[2]), "r"(a[3]), "r"(b0), "r"(b1));
}
__device__ __forceinline__ void split_store(float w, __nv_bfloat16* ph, __nv_bfloat16* pl) {
    __nv_bfloat16 h = __float2bfloat16(w);
    __nv_bfloat16 l = __float2bfloat16(w - __bfloat162float(h));
    *ph = h; *pl = l;
}

// ---------------- init: zero accum + split weights + composites ------------------
__global__ void init_kernel(const float* we,                 // w_email [128][64]
                            const float* be,                 // b_email [128]
                            const float* w1n, const float* w1r,
                            const float* b1,                 // b_l1_ue
                            const float* w2n, const float* w2r,
                            const float* w3n, const float* w3r)
{
    int i = blockIdx.x * blockDim.x + threadIdx.x;
    int stride = gridDim.x * blockDim.x;
    const int nE4 = NE * HDIM / 4;
    const int nUx4 = NU * 64 / 4;
    const int cE4 = NE / 4, cU4 = NU / 4;
    float4 z = make_float4(0.f, 0.f, 0.f, 0.f);
    float4* aE  = (float4*)g_accE;
    float4* aE2 = (float4*)g_accE2;
    for (int k = i; k < nE4; k += stride) { aE[k] = z; aE2[k] = z; }
    for (int k = i; k < nUx4; k += stride) ((float4*)g_accUx)[k] = z;
    for (int k = i; k < cE4; k += stride) ((float4*)g_cntE)[k] = z;
    for (int k = i; k < cU4; k += stride) ((float4*)g_cntU)[k] = z;
    // 6 direct weights [128 out][128 in]
    for (int k = i; k < 6 * 128 * 128; k += stride) {
        int m = k >> 14, r = k & 16383;
        int n = r >> 7, c = r & 127;
        const float* src;
        switch (m) {
            case 0: src = w1n; break;
            case 1: src = w1r; break;
            case 2: src = w2n; break;
            case 3: src = w2r; break;
            case 4: src = w3n; break;
            default: src = w3r; break;
        }
        split_store(src[n * 128 + c], &g_wh[m][n * WSTRIDE + c], &g_wl[m][n * WSTRIDE + c]);
    }
    // composites: Wc[m][n][c] = sum_j Wr[n][j] * we[j][c]   (m=0: W1r, m=1: W2n)
    for (int k = i; k < 2 * 128 * 64; k += stride) {
        int m = k >> 13, r = k & 8191;
        int n = r >> 6, c = r & 63;
        const float* Wr = m ? w2n : w1r;
        float s = 0.f;
#pragma unroll 4
        for (int j = 0; j < 128; j++) s += Wr[n * 128 + j] * we[j * 64 + c];
        split_store(s, &g_wch[m][n * WSTRIDE + c], &g_wcl[m][n * WSTRIDE + c]);
    }
    // bias vectors: g_bias1 = b_l1_ue + W1r@be ; g_gb2 = W2n@be
    for (int k = i; k < 2 * 128; k += stride) {
        int m = k >> 7, n = k & 127;
        const float* Wr = m ? w2n : w1r;
        float s = 0.f;
#pragma unroll 4
        for (int j = 0; j < 128; j++) s += Wr[n * 128 + j] * be[j];
        if (m == 0) g_bias1[n] = b1[n] + s;
        else        g_gb2[n] = s;
    }
}

// ---------------- edge scatter (128-dim): one warp per 8 edges, vector RED ------
__global__ void scatter_kernel(const int* __restrict__ src, const int* __restrict__ dst,
                               const float* __restrict__ xsrc,
                               float* __restrict__ accum, float* __restrict__ cnt,
                               int doCnt)
{
    int warp = (blockIdx.x * blockDim.x + threadIdx.x) >> 5;
    int lane = threadIdx.x & 31;
    int e0 = warp * 8;
    if (e0 >= NEDGE) return;
    int4 sa = *reinterpret_cast<const int4*>(src + e0);
    int4 sb = *reinterpret_cast<const int4*>(src + e0 + 4);
    int4 da = *reinterpret_cast<const int4*>(dst + e0);
    int4 db = *reinterpret_cast<const int4*>(dst + e0 + 4);
    int s[8] = {sa.x, sa.y, sa.z, sa.w, sb.x, sb.y, sb.z, sb.w};
    int d[8] = {da.x, da.y, da.z, da.w, db.x, db.y, db.z, db.w};
    float4 v[8];
#pragma unroll
    for (int i = 0; i < 8; i++)
        v[i] = *reinterpret_cast<const float4*>(xsrc + (size_t)s[i] * HDIM + lane * 4);
#pragma unroll
    for (int i = 0; i < 8; i++) {
        float* a = accum + (size_t)d[i] * HDIM + lane * 4;
        asm volatile("red.global.add.v4.f32 [%0], {%1, %2, %3, %4};"
                     :: "l"(a), "f"(v[i].x), "f"(v[i].y), "f"(v[i].z), "f"(v[i].w) : "memory");
    }
    if (doCnt && lane == 0) {
#pragma unroll
        for (int i = 0; i < 8; i++) {
            float one = 1.0f;
            asm volatile("red.global.add.f32 [%0], %1;" :: "l"(cnt + d[i]), "f"(one) : "memory");
        }
    }
}

// ---------------- edge scatter (64-dim): each half-warp handles 8 edges ---------
__global__ void scatter64_kernel(const int* __restrict__ src, const int* __restrict__ dst,
                                 const float* __restrict__ xsrc,   // [*,64]
                                 float* __restrict__ accum,        // [*,64]
                                 float* __restrict__ cnt)
{
    int warp = (blockIdx.x * blockDim.x + threadIdx.x) >> 5;
    int lane = threadIdx.x & 31;
    int half = lane >> 4, sub = lane & 15;
    int e0 = warp * 16 + half * 8;
    if (e0 >= NEDGE) return;
    int4 sa = *reinterpret_cast<const int4*>(src + e0);
    int4 sb = *reinterpret_cast<const int4*>(src + e0 + 4);
    int4 da = *reinterpret_cast<const int4*>(dst + e0);
    int4 db = *reinterpret_cast<const int4*>(dst + e0 + 4);
    int s[8] = {sa.x, sa.y, sa.z, sa.w, sb.x, sb.y, sb.z, sb.w};
    int d[8] = {da.x, da.y, da.z, da.w, db.x, db.y, db.z, db.w};
    float4 v[8];
#pragma unroll
    for (int i = 0; i < 8; i++)
        v[i] = *reinterpret_cast<const float4*>(xsrc + (size_t)s[i] * 64 + sub * 4);
#pragma unroll
    for (int i = 0; i < 8; i++) {
        float* a = accum + (size_t)d[i] * 64 + sub * 4;
        asm volatile("red.global.add.v4.f32 [%0], {%1, %2, %3, %4};"
                     :: "l"(a), "f"(v[i].x), "f"(v[i].y), "f"(v[i].z), "f"(v[i].w) : "memory");
    }
    if (sub == 0) {
#pragma unroll
        for (int i = 0; i < 8; i++) {
            float one = 1.0f;
            asm volatile("red.global.add.f32 [%0], %1;" :: "l"(cnt + d[i]), "f"(one) : "memory");
        }
    }
}

// ---------------- tensor-core combine GEMM (R12 core + runtime K2 + gated bias) --
// out[M,128] = relu( (A1*diag(1/max(cnt,1))) @ W1^T + A2 @ W2^T + bias
//                    + (gbias ? gbias*(cnt>0) : 0) )
// 8 warps: warp w owns rows (w>>1)*32..+31 x cols (w&1)*64..+63.
#define TILEB 34816u
__global__ void __launch_bounds__(256)
gemm_tc(const float* __restrict__ A1, int K1,
        const __nv_bfloat16* __restrict__ W1h, const __nv_bfloat16* __restrict__ W1l,
        const float* __restrict__ A2, int K2,
        const __nv_bfloat16* __restrict__ W2h, const __nv_bfloat16* __restrict__ W2l,
        const float* __restrict__ bias, const float* __restrict__ cnt,
        const float* __restrict__ gbias,
        float* __restrict__ out, int M)
{
    extern __shared__ char dsm[];
    uint32_t smBase = smem_u32(dsm);
    const uint32_t offAH = 0, offAL = TILEB;
    const uint32_t offW1h = 2 * TILEB, offW1l = 3 * TILEB;
    const uint32_t offW2h = 4 * TILEB, offW2l = 5 * TILEB;

    int tid = threadIdx.x;
    int widx = tid >> 5, lane = tid & 31;
    int rb = widx >> 1;
    int cb = widx & 1;
    int row0 = blockIdx.x * 128;

    {
        for (uint32_t i = tid * 16; i < TILEB; i += 256 * 16) {
            cp_async16(smBase + offW1h + i, (const char*)W1h + i);
            cp_async16(smBase + offW1l + i, (const char*)W1l + i);
            cp_async16(smBase + offW2h + i, (const char*)W2h + i);
            cp_async16(smBase + offW2l + i, (const char*)W2l + i);
        }
        cp_commit();
    }

    auto convA = [&](const float* A, int K, bool mean) {
        int r = tid >> 1;
        int half = tid & 1;
        int cw = K >> 1;
        int c0 = half * cw;
        int gr = row0 + r;
        float inv = 1.f;
        if (mean) {
            float cv = (gr < M) ? cnt[gr] : 1.f;
            inv = 1.f / fmaxf(cv, 1.f);
        }
        const float* Arow = A + (size_t)gr * K;
        char* pH = dsm + offAH + (uint32_t)r * 272u;
        char* pL = dsm + offAL + (uint32_t)r * 272u;
        for (int c = c0; c < c0 + cw; c += 4) {
            float4 a = make_float4(0.f, 0.f, 0.f, 0.f);
            if (gr < M) a = *reinterpret_cast<const float4*>(Arow + c);
            float v0 = a.x * inv, v1 = a.y * inv, v2 = a.z * inv, v3 = a.w * inv;
            __nv_bfloat16 h0 = __float2bfloat16(v0), h1 = __float2bfloat16(v1);
            __nv_bfloat16 h2 = __float2bfloat16(v2), h3 = __float2bfloat16(v3);
            __nv_bfloat16 l0 = __float2bfloat16(v0 - __bfloat162float(h0));
            __nv_bfloat16 l1 = __float2bfloat16(v1 - __bfloat162float(h1));
            __nv_bfloat16 l2 = __float2bfloat16(v2 - __bfloat162float(h2));
            __nv_bfloat16 l3 = __float2bfloat16(v3 - __bfloat162float(h3));
            *(uint32_t*)(pH + c * 2)     = pack_bf16(h0, h1);
            *(uint32_t*)(pH + c * 2 + 4) = pack_bf16(h2, h3);
            *(uint32_t*)(pL + c * 2)     = pack_bf16(l0, l1);
            *(uint32_t*)(pL + c * 2 + 4) = pack_bf16(l2, l3);
        }
    };

    float acc[16][4];
#pragma unroll
    for (int t = 0; t < 16; t++)
#pragma unroll
        for (int q = 0; q < 4; q++) acc[t][q] = 0.f;

    uint32_t aRowL = (uint32_t)(lane & 15);
    uint32_t aK8   = (uint32_t)((lane >> 4) * 8);
    uint32_t wN    = (uint32_t)((lane >> 4) * 8 + (lane & 7));
    uint32_t wK8   = (uint32_t)(((lane >> 3) & 1) * 8);

    for (int ph = 0; ph < 2; ph++) {
        const float* A = ph ? A2 : A1;
        int K = ph ? K2 : K1;
        uint32_t offh = ph ? offW2h : offW1h;
        uint32_t offl = ph ? offW2l : offW1l;
        if (ph) __syncthreads();
        convA(A, K, ph == 0);
        if (ph == 0) cp_wait_all();
        __syncthreads();

        int ksteps = K >> 4;
#pragma unroll 1
        for (int ks = 0; ks < ksteps; ks++) {
            uint32_t kb = (uint32_t)(ks * 16);
            uint32_t ah[2][4], al[2][4];
#pragma unroll
            for (int rt = 0; rt < 2; rt++) {
                uint32_t aoff = (((uint32_t)(rb * 32 + rt * 16) + aRowL) * WSTRIDE + kb + aK8) * 2;
                ldsm_x4(ah[rt], smBase + offAH + aoff);
                ldsm_x4(al[rt], smBase + offAL + aoff);
            }
            uint32_t bh[4][4], bl[4][4];
#pragma unroll
            for (int tp = 0; tp < 4; tp++) {
                uint32_t woff = (((uint32_t)(cb * 64 + tp * 16) + wN) * WSTRIDE + kb + wK8) * 2;
                ldsm_x4(bh[tp], smBase + offh + woff);
                ldsm_x4(bl[tp], smBase + offl + woff);
            }
#pragma unroll
            for (int rt = 0; rt < 2; rt++) {
#pragma unroll
                for (int tp = 0; tp < 4; tp++) {
                    int t0 = rt * 8 + tp * 2;
                    mma_bf16(acc[t0],     ah[rt], bh[tp][0], bh[tp][1]);
                    mma_bf16(acc[t0],     ah[rt], bl[tp][0], bl[tp][1]);
                    mma_bf16(acc[t0],     al[rt], bh[tp][0], bh[tp][1]);
                    mma_bf16(acc[t0 + 1], ah[rt], bh[tp][2], bh[tp][3]);
                    mma_bf16(acc[t0 + 1], ah[rt], bl[tp][2], bl[tp][3]);
                    mma_bf16(acc[t0 + 1], al[rt], bh[tp][2], bh[tp][3]);
                }
            }
        }
    }

    // epilogue
#pragma unroll
    for (int rt = 0; rt < 2; rt++) {
        int gr0 = row0 + rb * 32 + rt * 16 + (lane >> 2);
        int gr1 = gr0 + 8;
        float gf0 = 0.f, gf1 = 0.f;
        if (gbias) {
            gf0 = (gr0 < M && cnt[gr0] > 0.5f) ? 1.f : 0.f;
            gf1 = (gr1 < M && cnt[gr1] > 0.5f) ? 1.f : 0.f;
        }
#pragma unroll
        for (int j = 0; j < 8; j++) {
            int col = cb * 64 + j * 8 + (lane & 3) * 2;
            float b0 = bias[col], b1 = bias[col + 1];
            float g0 = 0.f, g1 = 0.f;
            if (gbias) { g0 = gbias[col]; g1 = gbias[col + 1]; }
            float* a = acc[rt * 8 + j];
            float d0 = fmaxf(a[0] + b0 + g0 * gf0, 0.f);
            float d1 = fmaxf(a[1] + b1 + g1 * gf0, 0.f);
            float d2 = fmaxf(a[2] + b0 + g0 * gf1, 0.f);
            float d3 = fmaxf(a[3] + b1 + g1 * gf1, 0.f);
            if (gr0 < M) *reinterpret_cast<float2*>(out + (size_t)gr0 * 128 + col) = make_float2(d0, d1);
            if (gr1 < M) *reinterpret_cast<float2*>(out + (size_t)gr1 * 128 + col) = make_float2(d2, d3);
        }
    }
}

// ---------------- B-spline bases (uniform grid, grid_size=5, k=3 -> 8 bases) ----
__device__ __forceinline__ void bspline8(float x, float b[8]) {
    const float hstep = 2.0f / 5.0f;
    float g[12];
#pragma unroll
    for (int t = 0; t < 12; t++) g[t] = (float)(t - 3) * hstep - 1.0f;
    float p0[11], p1[10], p2[9];
#pragma unroll
    for (int t = 0; t < 11; t++) p0[t] = (x >= g[t] && x < g[t + 1]) ? 1.0f : 0.0f;
#pragma unroll
    for (int t = 0; t < 10; t++)
        p1[t] = ((x - g[t]) * (1.0f / (g[t + 1] - g[t]))) * p0[t]
              + ((g[t + 2] - x) * (1.0f / (g[t + 2] - g[t + 1]))) * p0[t + 1];
#pragma unroll
    for (int t = 0; t < 9; t++)
        p2[t] = ((x - g[t]) * (1.0f / (g[t + 2] - g[t]))) * p1[t]
              + ((g[t + 3] - x) * (1.0f / (g[t + 3] - g[t + 1]))) * p1[t + 1];
#pragma unroll
    for (int t = 0; t < 8; t++)
        b[t] = ((x - g[t]) * (1.0f / (g[t + 3] - g[t]))) * p2[t]
             + ((g[t + 4] - x) * (1.0f / (g[t + 4] - g[t + 1]))) * p2[t + 1];
}

__device__ __forceinline__ float silu(float x) {
    return x / (1.0f + __expf(-x));
}

// ---------------- KAN layer 1 (unchanged, known-good) -----------------------------
__global__ void __launch_bounds__(256)
kan1_kernel(const float* __restrict__ x,
            const float* __restrict__ spline,
            const float* __restrict__ scaler,
            const float* __restrict__ basew,
            float* __restrict__ out, int M)
{
    __shared__ __align__(16) float Bs[2][32][130];
    __shared__ __align__(16) float Ws[2][32][66];
    int tid = threadIdx.x;
    int ty = tid >> 4, tx = tid & 15;
    int row0 = blockIdx.x * 128;
    unsigned long long acc[4][4];
#pragma unroll
    for (int p = 0; p < 4; p++)
#pragma unroll
        for (int j = 0; j < 4; j++) acc[p][j] = 0ULL;

    auto fill_chunk = [&](int c, float nb[2][8], float nw[8]) {
        int f0 = c * 4;
#pragma unroll
        for (int it = 0; it < 2; it++) {
            int p = tid + it * 256;
            int feat = p & 3, r = p >> 2;
            int gr = row0 + r;
            float xv = (gr < M) ? x[(size_t)gr * 128 + f0 + feat] : 0.f;
            bspline8(xv, nb[it]);
        }
#pragma unroll
        for (int it = 0; it < 8; it++) {
            int idx = tid + it * 256;
            int kk = idx & 31, col = idx >> 5;
            nw[it] = spline[(size_t)col * 1024 + f0 * 8 + kk] * scaler[col * 128 + f0 + (kk >> 3)];
        }
    };
    auto sts_chunk = [&](const float nb[2][8], const float nw[8], int buf) {
#pragma unroll
        for (int it = 0; it < 2; it++) {
            int p = tid + it * 256;
            int feat = p & 3, r = p >> 2;
#pragma unroll
            for (int t = 0; t < 8; t++) Bs[buf][feat * 8 + t][r] = nb[it][t];
        }
#pragma unroll
        for (int it = 0; it < 8; it++) {
            int idx = tid + it * 256;
            Ws[buf][idx & 31][idx >> 5] = nw[it];
        }
    };

    {
        float nb[2][8], nw[8];
        fill_chunk(0, nb, nw);
        sts_chunk(nb, nw, 0);
    }
    __syncthreads();

    for (int c = 0; c < 32; c++) {
        int cur = c & 1;
        float nb[2][8], nw[8];
        if (c + 1 < 32) fill_chunk(c + 1, nb, nw);
#pragma unroll
        for (int kk = 0; kk < 32; kk++) {
            unsigned long long a2[4];
#pragma unroll
            for (int p = 0; p < 4; p++)
                a2[p] = *reinterpret_cast<const unsigned long long*>(&Bs[cur][kk][ty * 8 + 2 * p]);
            unsigned long long wd[4];
#pragma unroll
            for (int j = 0; j < 4; j++) wd[j] = dup_x2(Ws[cur][kk][tx + 16 * j]);
#pragma unroll
            for (int p = 0; p < 4; p++)
#pragma unroll
                for (int j = 0; j < 4; j++) fma_x2(acc[p][j], a2[p], wd[j]);
        }
        if (c + 1 < 32) sts_chunk(nb, nw, cur ^ 1);
        __syncthreads();
    }

    for (int f0 = 0; f0 < 128; f0 += 32) {
#pragma unroll
        for (int it = 0; it < 16; it++) {
            int p = tid + it * 256;
            int feat = p & 31, r = p >> 5;
            int gr = row0 + r;
            float xv = (gr < M) ? x[(size_t)gr * 128 + f0 + feat] : 0.f;
            Bs[0][feat][r] = silu(xv);
        }
#pragma unroll
        for (int it = 0; it < 8; it++) {
            int idx = tid + it * 256;
            int kk = idx & 31, col = idx >> 5;
            Ws[0][kk][col] = basew[(size_t)col * 128 + f0 + kk];
        }
        __syncthreads();
#pragma unroll
        for (int kk = 0; kk < 32; kk++) {
            unsigned long long a2[4];
#pragma unroll
            for (int p = 0; p < 4; p++)
                a2[p] = *reinterpret_cast<const unsigned long long*>(&Bs[0][kk][ty * 8 + 2 * p]);
            unsigned long long wd[4];
#pragma unroll
            for (int j = 0; j < 4; j++) wd[j] = dup_x2(Ws[0][kk][tx + 16 * j]);
#pragma unroll
            for (int p = 0; p < 4; p++)
#pragma unroll
                for (int j = 0; j < 4; j++) fma_x2(acc[p][j], a2[p], wd[j]);
        }
        __syncthreads();
    }

#pragma unroll
    for (int p = 0; p < 4; p++) {
        int gr0 = row0 + ty * 8 + 2 * p;
        int gr1 = gr0 + 1;
        float r0[4], r1[4];
#pragma unroll
        for (int j = 0; j < 4; j++) unpack_x2(acc[p][j], r0[j], r1[j]);
        if (gr0 < M) {
#pragma unroll
            for (int j = 0; j < 4; j++) out[(size_t)gr0 * 64 + tx + 16 * j] = r0[j];
        }
        if (gr1 < M) {
#pragma unroll
            for (int j = 0; j < 4; j++) out[(size_t)gr1 * 64 + tx + 16 * j] = r1[j];
        }
    }
}

// ---------------- KAN layer 2 (unchanged) ----------------------------------------
__global__ void kan2_kernel(const float* __restrict__ hin,
                            const float* __restrict__ spline,
                            const float* __restrict__ scaler,
                            const float* __restrict__ basew,
                            float* __restrict__ out, int M)
{
    __shared__ float sh[128][65];
    __shared__ float sw[2][64][8];
    __shared__ float sb[2][64];
    int tid = threadIdx.x;
    int row0 = blockIdx.x * 128;
    for (int idx = tid; idx < 1024; idx += 128) {
        int o = idx >> 9, rem = idx & 511, f = rem >> 3, t = rem & 7;
        sw[o][f][t] = spline[idx] * scaler[o * 64 + f];
    }
    if (tid < 128) sb[tid >> 6][tid & 63] = basew[tid];
    for (int idx = tid; idx < 128 * 64; idx += 128) {
        int r = idx >> 6, f = idx & 63;
        int gr = row0 + r;
        sh[r][f] = (gr < M) ? hin[(size_t)gr * 64 + f] : 0.f;
    }
    __syncthreads();
    int gr = row0 + tid;
    if (gr >= M) return;
    float acc0 = 0.f, acc1 = 0.f;
    for (int f = 0; f < 64; f++) {
        float xv = sh[tid][f];
        float s = silu(xv);
        acc0 += s * sb[0][f];
        acc1 += s * sb[1][f];
        float b[8];
        bspline8(xv, b);
#pragma unroll
        for (int t = 0; t < 8; t++) {
            acc0 += b[t] * sw[0][f][t];
            acc1 += b[t] * sw[1][f][t];
        }
    }
    out[(size_t)gr * 2 + 0] = acc0;
    out[(size_t)gr * 2 + 1] = acc1;
}

// ---------------- launch ----------------
extern "C" void kernel_launch(void* const* d_in, const int* in_sizes, int n_in,
                              void* d_out, int out_size)
{
    const float* x_email    = (const float*)d_in[0];
    const int*   ei_ue      = (const int*)d_in[1];
    const int*   ei_eu      = (const int*)d_in[2];
    const float* w_email    = (const float*)d_in[3];
    const float* b_email    = (const float*)d_in[4];
    const float* emb_user   = (const float*)d_in[5];
    const float* w_l1_ue_n  = (const float*)d_in[6];
    const float* b_l1_ue    = (const float*)d_in[7];
    const float* w_l1_ue_r  = (const float*)d_in[8];
    const float* w_l1_eu_n  = (const float*)d_in[9];
    const float* b_l1_eu    = (const float*)d_in[10];
    const float* w_l1_eu_r  = (const float*)d_in[11];
    const float* w_l2_ue_n  = (const float*)d_in[12];
    const float* b_l2_ue    = (const float*)d_in[13];
    const float* w_l2_ue_r  = (const float*)d_in[14];
    const float* kan1_base   = (const float*)d_in[18];
    const float* kan1_spline = (const float*)d_in[19];
    const float* kan1_scaler = (const float*)d_in[20];
    const float* kan2_base   = (const float*)d_in[22];
    const float* kan2_spline = (const float*)d_in[23];
    const float* kan2_scaler = (const float*)d_in[24];
    float* out = (float*)d_out;

    float *xe, *accE, *accE2, *e1, *accUx, *u1, *hbuf, *cntE, *cntU, *bias1, *gb2;
    cudaGetSymbolAddress((void**)&xe,    g_xe);
    cudaGetSymbolAddress((void**)&accE,  g_accE);
    cudaGetSymbolAddress((void**)&accE2, g_accE2);
    cudaGetSymbolAddress((void**)&e1,    g_e1);
    cudaGetSymbolAddress((void**)&accUx, g_accUx);
    cudaGetSymbolAddress((void**)&u1,    g_u1);
    cudaGetSymbolAddress((void**)&hbuf,  g_h);
    cudaGetSymbolAddress((void**)&cntE,  g_cntE);
    cudaGetSymbolAddress((void**)&cntU,  g_cntU);
    cudaGetSymbolAddress((void**)&bias1, g_bias1);
    cudaGetSymbolAddress((void**)&gb2,   g_gb2);
    __nv_bfloat16 *wh, *wl, *wch, *wcl;
    cudaGetSymbolAddress((void**)&wh,  g_wh);
    cudaGetSymbolAddress((void**)&wl,  g_wl);
    cudaGetSymbolAddress((void**)&wch, g_wch);
    cudaGetSymbolAddress((void**)&wcl, g_wcl);
    auto WH = [&](int m) { return wh + (size_t)m * 128 * WSTRIDE; };
    auto WL = [&](int m) { return wl + (size_t)m * 128 * WSTRIDE; };
    auto WCH = [&](int m) { return wch + (size_t)m * 128 * WSTRIDE; };
    auto WCL = [&](int m) { return wcl + (size_t)m * 128 * WSTRIDE; };

    const int gE = (NE + 127) / 128;   // 1563
    const int gU = (NU + 127) / 128;   // 782
    const int gScat = (NEDGE / 8 * 32 + 255) / 256;    // 15625
    const int gScat64 = (NEDGE / 16 * 32 + 255) / 256; // 7813

    const int SMEM_TC = (int)(6 * TILEB);
    cudaFuncSetAttribute(gemm_tc, cudaFuncAttributeMaxDynamicSharedMemorySize, SMEM_TC);

    // 0: init (zero + weight split + composites)
    init_kernel<<<4096, 256>>>(w_email, b_email, w_l1_ue_n, w_l1_ue_r, b_l1_ue,
                               w_l1_eu_n, w_l1_eu_r, w_l2_ue_n, w_l2_ue_r);
    // 1: conv1 email aggregate (emb_user -> accE)
    scatter_kernel<<<gScat, 256>>>(ei_ue, ei_ue + NEDGE, emb_user, accE, cntE, 1);
    // 2: conv1 user aggregate (x_email 64-dim -> accUx)
    scatter64_kernel<<<gScat64, 256>>>(ei_eu, ei_eu + NEDGE, x_email, accUx, cntU);
    // 3: conv1 email combine: mean(accE)@W1n + x_email@Wc1 + bias1
    gemm_tc<<<gE, 256, SMEM_TC>>>(accE, 128, WH(0), WL(0),
                                  x_email, 64, WCH(0), WCL(0),
                                  bias1, cntE, nullptr, e1, NE);
    // 4: conv1 user combine: mean(accUx)@Wc2 + emb_user@W2r + b_l1_eu + gated gb2
    gemm_tc<<<gU, 256, SMEM_TC>>>(accUx, 64, WCH(1), WCL(1),
                                  emb_user, 128, WH(3), WL(3),
                                  b_l1_eu, cntU, gb2, u1, NU);
    // 5: conv2 email aggregate (u1 -> accE2)
    scatter_kernel<<<gScat, 256>>>(ei_ue, ei_ue + NEDGE, u1, accE2, nullptr, 0);
    // 6: conv2 email combine
    gemm_tc<<<gE, 256, SMEM_TC>>>(accE2, 128, WH(4), WL(4),
                                  e1, 128, WH(5), WL(5),
                                  b_l2_ue, cntE, nullptr, xe /*= e2*/, NE);
    // 7-8: KAN head
    kan1_kernel<<<gE, 256>>>(xe, kan1_spline, kan1_scaler, kan1_base, hbuf, NE);
    kan2_kernel<<<gE, 128>>>(hbuf, kan2_spline, kan2_scaler, kan2_base, out, NE);
}

// round 16
// speedup vs baseline: 1.4572x; 1.3181x over previous
#include <cuda_runtime.h>
#include <cuda_bf16.h>
#include <math.h>
#include <stdint.h>

#define NE 200000
#define NU 100000
#define NEDGE 1000000
#define HDIM 128

// ---------------- scratch (static device arrays; no allocation) ----------------
__device__ float g_xe[(size_t)NE * HDIM];     // e2 lives here
__device__ float g_accE[(size_t)NE * HDIM];
__device__ float g_accE2[(size_t)NE * HDIM];
__device__ float g_e1[(size_t)NE * HDIM];
__device__ float g_accUx[(size_t)NU * 64];    // x_email aggregated (64-dim)
__device__ float g_u1[(size_t)NU * HDIM];
__device__ float g_h[(size_t)NE * 64];
__device__ float g_cntE[NE];
__device__ float g_cntU[NU];
__device__ float g_bias1[128];                // b_l1_ue + W1r@b_email
__device__ float g_gb2[128];                  // W2n@b_email (gated by cntU>0)
// bf16 hi/lo weight tiles, padded row stride 136 (272B -> conflict-free ldmatrix)
#define WSTRIDE 136
__device__ __align__(16) __nv_bfloat16 g_wh[6][128 * WSTRIDE];
__device__ __align__(16) __nv_bfloat16 g_wl[6][128 * WSTRIDE];
__device__ __align__(16) __nv_bfloat16 g_wch[2][128 * WSTRIDE];  // composites (K=64)
__device__ __align__(16) __nv_bfloat16 g_wcl[2][128 * WSTRIDE];
// kan1 weight chunks: [9][64][136]; c<8: spline*scaler (16 feats x 6 bases), c=8: base_w
#define K1CH 8704   // 64*136
__device__ __align__(16) __nv_bfloat16 g_k1wh[9 * K1CH];
__device__ __align__(16) __nv_bfloat16 g_k1wl[9 * K1CH];

// ---------------- helpers ----------------
__device__ __forceinline__ uint32_t smem_u32(const void* p) {
    return (uint32_t)__cvta_generic_to_shared(p);
}
__device__ __forceinline__ void cp_async16(uint32_t dst, const void* src) {
    asm volatile("cp.async.ca.shared.global [%0], [%1], 16;" :: "r"(dst), "l"(src));
}
__device__ __forceinline__ void cp_commit() { asm volatile("cp.async.commit_group;"); }
__device__ __forceinline__ void cp_wait_all() {
    asm volatile("cp.async.wait_group 0;" ::: "memory");
}
__device__ __forceinline__ uint32_t pack_bf16(__nv_bfloat16 a, __nv_bfloat16 b) {
    uint16_t ua = *(uint16_t*)&a, ub = *(uint16_t*)&b;
    return (uint32_t)ua | ((uint32_t)ub << 16);
}
__device__ __forceinline__ void ldsm_x4(uint32_t r[4], uint32_t addr) {
    asm volatile("ldmatrix.sync.aligned.m8n8.x4.shared.b16 {%0,%1,%2,%3}, [%4];"
                 : "=r"(r[0]), "=r"(r[1]), "=r"(r[2]), "=r"(r[3]) : "r"(addr));
}
__device__ __forceinline__ void mma_bf16(float d[4], const uint32_t a[4],
                                         uint32_t b0, uint32_t b1) {
    asm volatile(
        "mma.sync.aligned.m16n8k16.row.col.f32.bf16.bf16.f32 "
        "{%0,%1,%2,%3}, {%4,%5,%6,%7}, {%8,%9}, {%0,%1,%2,%3};"
        : "+f"(d[0]), "+f"(d[1]), "+f"(d[2]), "+f"(d[3])
        : "r"(a[0]), "r"(a[1]), "r"(a[2]), "r"(a[3]), "r"(b0), "r"(b1));
}
__device__ __forceinline__ void split_store(float w, __nv_bfloat16* ph, __nv_bfloat16* pl) {
    __nv_bfloat16 h = __float2bfloat16(w);
    __nv_bfloat16 l = __float2bfloat16(w - __bfloat162float(h));
    *ph = h; *pl = l;
}
__device__ __forceinline__ void split2(float v, __nv_bfloat16& h, __nv_bfloat16& l) {
    h = __float2bfloat16(v);
    l = __float2bfloat16(v - __bfloat162float(h));
}

// ---------------- B-spline bases (uniform grid, grid_size=5, k=3 -> 8 bases) ----
__device__ __forceinline__ void bspline8(float x, float b[8]) {
    const float hstep = 2.0f / 5.0f;
    float g[12];
#pragma unroll
    for (int t = 0; t < 12; t++) g[t] = (float)(t - 3) * hstep - 1.0f;
    float p0[11], p1[10], p2[9];
#pragma unroll
    for (int t = 0; t < 11; t++) p0[t] = (x >= g[t] && x < g[t + 1]) ? 1.0f : 0.0f;
#pragma unroll
    for (int t = 0; t < 10; t++)
        p1[t] = ((x - g[t]) * (1.0f / (g[t + 1] - g[t]))) * p0[t]
              + ((g[t + 2] - x) * (1.0f / (g[t + 2] - g[t + 1]))) * p0[t + 1];
#pragma unroll
    for (int t = 0; t < 9; t++)
        p2[t] = ((x - g[t]) * (1.0f / (g[t + 2] - g[t]))) * p1[t]
              + ((g[t + 3] - x) * (1.0f / (g[t + 3] - g[t + 1]))) * p1[t + 1];
#pragma unroll
    for (int t = 0; t < 8; t++)
        b[t] = ((x - g[t]) * (1.0f / (g[t + 3] - g[t]))) * p2[t]
             + ((g[t + 4] - x) * (1.0f / (g[t + 4] - g[t + 1]))) * p2[t + 1];
}

__device__ __forceinline__ float silu(float x) {
    return x / (1.0f + __expf(-x));
}

// ---------------- init: zero accum + split weights + composites + kan1 chunks ----
__global__ void init_kernel(const float* we, const float* be,
                            const float* w1n, const float* w1r, const float* b1,
                            const float* w2n, const float* w2r,
                            const float* w3n, const float* w3r,
                            const float* k1spline, const float* k1scaler,
                            const float* k1base)
{
    int i = blockIdx.x * blockDim.x + threadIdx.x;
    int stride = gridDim.x * blockDim.x;
    const int nE4 = NE * HDIM / 4;
    const int nUx4 = NU * 64 / 4;
    const int cE4 = NE / 4, cU4 = NU / 4;
    float4 z = make_float4(0.f, 0.f, 0.f, 0.f);
    float4* aE  = (float4*)g_accE;
    float4* aE2 = (float4*)g_accE2;
    for (int k = i; k < nE4; k += stride) { aE[k] = z; aE2[k] = z; }
    for (int k = i; k < nUx4; k += stride) ((float4*)g_accUx)[k] = z;
    for (int k = i; k < cE4; k += stride) ((float4*)g_cntE)[k] = z;
    for (int k = i; k < cU4; k += stride) ((float4*)g_cntU)[k] = z;
    for (int k = i; k < 6 * 128 * 128; k += stride) {
        int m = k >> 14, r = k & 16383;
        int n = r >> 7, c = r & 127;
        const float* src;
        switch (m) {
            case 0: src = w1n; break;
            case 1: src = w1r; break;
            case 2: src = w2n; break;
            case 3: src = w2r; break;
            case 4: src = w3n; break;
            default: src = w3r; break;
        }
        split_store(src[n * 128 + c], &g_wh[m][n * WSTRIDE + c], &g_wl[m][n * WSTRIDE + c]);
    }
    for (int k = i; k < 2 * 128 * 64; k += stride) {
        int m = k >> 13, r = k & 8191;
        int n = r >> 6, c = r & 63;
        const float* Wr = m ? w2n : w1r;
        float s = 0.f;
#pragma unroll 4
        for (int j = 0; j < 128; j++) s += Wr[n * 128 + j] * we[j * 64 + c];
        split_store(s, &g_wch[m][n * WSTRIDE + c], &g_wcl[m][n * WSTRIDE + c]);
    }
    for (int k = i; k < 2 * 128; k += stride) {
        int m = k >> 7, n = k & 127;
        const float* Wr = m ? w2n : w1r;
        float s = 0.f;
#pragma unroll 4
        for (int j = 0; j < 128; j++) s += Wr[n * 128 + j] * be[j];
        if (m == 0) g_bias1[n] = b1[n] + s;
        else        g_gb2[n] = s;
    }
    // kan1 chunked weights: c<8 -> [64 n][96 cols: f_local*6+tt (tt=basis 2..7)]
    for (int k = i; k < 9 * K1CH; k += stride) {
        int c = k / K1CH, r = k % K1CH;
        int n = r / 136, col = r % 136;
        float w = 0.f;
        if (c < 8) {
            if (col < 96) {
                int f = 16 * c + col / 6, tt = col % 6;
                w = k1spline[(size_t)n * 1024 + f * 8 + tt + 2] * k1scaler[n * 128 + f];
            }
        } else {
            if (col < 128) w = k1base[n * 128 + col];
        }
        split_store(w, &g_k1wh[k], &g_k1wl[k]);
    }
}

// ---------------- edge scatter (128-dim): one warp per 8 edges, vector RED ------
__global__ void scatter_kernel(const int* __restrict__ src, const int* __restrict__ dst,
                               const float* __restrict__ xsrc,
                               float* __restrict__ accum, float* __restrict__ cnt,
                               int doCnt)
{
    int warp = (blockIdx.x * blockDim.x + threadIdx.x) >> 5;
    int lane = threadIdx.x & 31;
    int e0 = warp * 8;
    if (e0 >= NEDGE) return;
    int4 sa = *reinterpret_cast<const int4*>(src + e0);
    int4 sb = *reinterpret_cast<const int4*>(src + e0 + 4);
    int4 da = *reinterpret_cast<const int4*>(dst + e0);
    int4 db = *reinterpret_cast<const int4*>(dst + e0 + 4);
    int s[8] = {sa.x, sa.y, sa.z, sa.w, sb.x, sb.y, sb.z, sb.w};
    int d[8] = {da.x, da.y, da.z, da.w, db.x, db.y, db.z, db.w};
    float4 v[8];
#pragma unroll
    for (int i = 0; i < 8; i++)
        v[i] = *reinterpret_cast<const float4*>(xsrc + (size_t)s[i] * HDIM + lane * 4);
#pragma unroll
    for (int i = 0; i < 8; i++) {
        float* a = accum + (size_t)d[i] * HDIM + lane * 4;
        asm volatile("red.global.add.v4.f32 [%0], {%1, %2, %3, %4};"
                     :: "l"(a), "f"(v[i].x), "f"(v[i].y), "f"(v[i].z), "f"(v[i].w) : "memory");
    }
    if (doCnt && lane == 0) {
#pragma unroll
        for (int i = 0; i < 8; i++) {
            float one = 1.0f;
            asm volatile("red.global.add.f32 [%0], %1;" :: "l"(cnt + d[i]), "f"(one) : "memory");
        }
    }
}

// ---------------- edge scatter (64-dim): each half-warp handles 8 edges ---------
__global__ void scatter64_kernel(const int* __restrict__ src, const int* __restrict__ dst,
                                 const float* __restrict__ xsrc,
                                 float* __restrict__ accum,
                                 float* __restrict__ cnt)
{
    int warp = (blockIdx.x * blockDim.x + threadIdx.x) >> 5;
    int lane = threadIdx.x & 31;
    int half = lane >> 4, sub = lane & 15;
    int e0 = warp * 16 + half * 8;
    if (e0 >= NEDGE) return;
    int4 sa = *reinterpret_cast<const int4*>(src + e0);
    int4 sb = *reinterpret_cast<const int4*>(src + e0 + 4);
    int4 da = *reinterpret_cast<const int4*>(dst + e0);
    int4 db = *reinterpret_cast<const int4*>(dst + e0 + 4);
    int s[8] = {sa.x, sa.y, sa.z, sa.w, sb.x, sb.y, sb.z, sb.w};
    int d[8] = {da.x, da.y, da.z, da.w, db.x, db.y, db.z, db.w};
    float4 v[8];
#pragma unroll
    for (int i = 0; i < 8; i++)
        v[i] = *reinterpret_cast<const float4*>(xsrc + (size_t)s[i] * 64 + sub * 4);
#pragma unroll
    for (int i = 0; i < 8; i++) {
        float* a = accum + (size_t)d[i] * 64 + sub * 4;
        asm volatile("red.global.add.v4.f32 [%0], {%1, %2, %3, %4};"
                     :: "l"(a), "f"(v[i].x), "f"(v[i].y), "f"(v[i].z), "f"(v[i].w) : "memory");
    }
    if (sub == 0) {
#pragma unroll
        for (int i = 0; i < 8; i++) {
            float one = 1.0f;
            asm volatile("red.global.add.f32 [%0], %1;" :: "l"(cnt + d[i]), "f"(one) : "memory");
        }
    }
}

// ---------------- tensor-core combine GEMM (unchanged from R15) ------------------
#define TILEB 34816u
__global__ void __launch_bounds__(256)
gemm_tc(const float* __restrict__ A1, int K1,
        const __nv_bfloat16* __restrict__ W1h, const __nv_bfloat16* __restrict__ W1l,
        const float* __restrict__ A2, int K2,
        const __nv_bfloat16* __restrict__ W2h, const __nv_bfloat16* __restrict__ W2l,
        const float* __restrict__ bias, const float* __restrict__ cnt,
        const float* __restrict__ gbias,
        float* __restrict__ out, int M)
{
    extern __shared__ char dsm[];
    uint32_t smBase = smem_u32(dsm);
    const uint32_t offAH = 0, offAL = TILEB;
    const uint32_t offW1h = 2 * TILEB, offW1l = 3 * TILEB;
    const uint32_t offW2h = 4 * TILEB, offW2l = 5 * TILEB;

    int tid = threadIdx.x;
    int widx = tid >> 5, lane = tid & 31;
    int rb = widx >> 1;
    int cb = widx & 1;
    int row0 = blockIdx.x * 128;

    {
        for (uint32_t i = tid * 16; i < TILEB; i += 256 * 16) {
            cp_async16(smBase + offW1h + i, (const char*)W1h + i);
            cp_async16(smBase + offW1l + i, (const char*)W1l + i);
            cp_async16(smBase + offW2h + i, (const char*)W2h + i);
            cp_async16(smBase + offW2l + i, (const char*)W2l + i);
        }
        cp_commit();
    }

    auto convA = [&](const float* A, int K, bool mean) {
        int r = tid >> 1;
        int half = tid & 1;
        int cw = K >> 1;
        int c0 = half * cw;
        int gr = row0 + r;
        float inv = 1.f;
        if (mean) {
            float cv = (gr < M) ? cnt[gr] : 1.f;
            inv = 1.f / fmaxf(cv, 1.f);
        }
        const float* Arow = A + (size_t)gr * K;
        char* pH = dsm + offAH + (uint32_t)r * 272u;
        char* pL = dsm + offAL + (uint32_t)r * 272u;
        for (int c = c0; c < c0 + cw; c += 4) {
            float4 a = make_float4(0.f, 0.f, 0.f, 0.f);
            if (gr < M) a = *reinterpret_cast<const float4*>(Arow + c);
            float v0 = a.x * inv, v1 = a.y * inv, v2 = a.z * inv, v3 = a.w * inv;
            __nv_bfloat16 h0, h1, h2, h3, l0, l1, l2, l3;
            split2(v0, h0, l0); split2(v1, h1, l1);
            split2(v2, h2, l2); split2(v3, h3, l3);
            *(uint32_t*)(pH + c * 2)     = pack_bf16(h0, h1);
            *(uint32_t*)(pH + c * 2 + 4) = pack_bf16(h2, h3);
            *(uint32_t*)(pL + c * 2)     = pack_bf16(l0, l1);
            *(uint32_t*)(pL + c * 2 + 4) = pack_bf16(l2, l3);
        }
    };

    float acc[16][4];
#pragma unroll
    for (int t = 0; t < 16; t++)
#pragma unroll
        for (int q = 0; q < 4; q++) acc[t][q] = 0.f;

    uint32_t aRowL = (uint32_t)(lane & 15);
    uint32_t aK8   = (uint32_t)((lane >> 4) * 8);
    uint32_t wN    = (uint32_t)((lane >> 4) * 8 + (lane & 7));
    uint32_t wK8   = (uint32_t)(((lane >> 3) & 1) * 8);

    for (int ph = 0; ph < 2; ph++) {
        const float* A = ph ? A2 : A1;
        int K = ph ? K2 : K1;
        uint32_t offh = ph ? offW2h : offW1h;
        uint32_t offl = ph ? offW2l : offW1l;
        if (ph) __syncthreads();
        convA(A, K, ph == 0);
        if (ph == 0) cp_wait_all();
        __syncthreads();

        int ksteps = K >> 4;
#pragma unroll 1
        for (int ks = 0; ks < ksteps; ks++) {
            uint32_t kb = (uint32_t)(ks * 16);
            uint32_t ah[2][4], al[2][4];
#pragma unroll
            for (int rt = 0; rt < 2; rt++) {
                uint32_t aoff = (((uint32_t)(rb * 32 + rt * 16) + aRowL) * WSTRIDE + kb + aK8) * 2;
                ldsm_x4(ah[rt], smBase + offAH + aoff);
                ldsm_x4(al[rt], smBase + offAL + aoff);
            }
            uint32_t bh[4][4], bl[4][4];
#pragma unroll
            for (int tp = 0; tp < 4; tp++) {
                uint32_t woff = (((uint32_t)(cb * 64 + tp * 16) + wN) * WSTRIDE + kb + wK8) * 2;
                ldsm_x4(bh[tp], smBase + offh + woff);
                ldsm_x4(bl[tp], smBase + offl + woff);
            }
#pragma unroll
            for (int rt = 0; rt < 2; rt++) {
#pragma unroll
                for (int tp = 0; tp < 4; tp++) {
                    int t0 = rt * 8 + tp * 2;
                    mma_bf16(acc[t0],     ah[rt], bh[tp][0], bh[tp][1]);
                    mma_bf16(acc[t0],     ah[rt], bl[tp][0], bl[tp][1]);
                    mma_bf16(acc[t0],     al[rt], bh[tp][0], bh[tp][1]);
                    mma_bf16(acc[t0 + 1], ah[rt], bh[tp][2], bh[tp][3]);
                    mma_bf16(acc[t0 + 1], ah[rt], bl[tp][2], bl[tp][3]);
                    mma_bf16(acc[t0 + 1], al[rt], bh[tp][2], bh[tp][3]);
                }
            }
        }
    }

#pragma unroll
    for (int rt = 0; rt < 2; rt++) {
        int gr0 = row0 + rb * 32 + rt * 16 + (lane >> 2);
        int gr1 = gr0 + 8;
        float gf0 = 0.f, gf1 = 0.f;
        if (gbias) {
            gf0 = (gr0 < M && cnt[gr0] > 0.5f) ? 1.f : 0.f;
            gf1 = (gr1 < M && cnt[gr1] > 0.5f) ? 1.f : 0.f;
        }
#pragma unroll
        for (int j = 0; j < 8; j++) {
            int col = cb * 64 + j * 8 + (lane & 3) * 2;
            float b0 = bias[col], b1 = bias[col + 1];
            float g0 = 0.f, g1 = 0.f;
            if (gbias) { g0 = gbias[col]; g1 = gbias[col + 1]; }
            float* a = acc[rt * 8 + j];
            float d0 = fmaxf(a[0] + b0 + g0 * gf0, 0.f);
            float d1 = fmaxf(a[1] + b1 + g1 * gf0, 0.f);
            float d2 = fmaxf(a[2] + b0 + g0 * gf1, 0.f);
            float d3 = fmaxf(a[3] + b1 + g1 * gf1, 0.f);
            if (gr0 < M) *reinterpret_cast<float2*>(out + (size_t)gr0 * 128 + col) = make_float2(d0, d1);
            if (gr1 < M) *reinterpret_cast<float2*>(out + (size_t)gr1 * 128 + col) = make_float2(d2, d3);
        }
    }
}

// ---------------- KAN layer 1: tensor-core, 6-basis (input >= 0), chunked --------
// out[M,64] = B(x) @ (spline*scaler)^T + silu(x) @ base^T
// 9 chunks: c<8 -> 16 feats x 6 bases (K=96); c=8 -> silu base (K=128).
// Warp w: rows (w>>1)*32..+31, cols (w&1)*32..+31. smem 104448 -> 2 CTAs/SM.
#define K1WT 17408u
__global__ void __launch_bounds__(256, 2)
kan1_tc(const float* __restrict__ x,           // [M,128]
        const __nv_bfloat16* __restrict__ Wh,  // [9][64*136]
        const __nv_bfloat16* __restrict__ Wl,
        float* __restrict__ out, int M)        // [M,64]
{
    extern __shared__ char dsm[];
    uint32_t smBase = smem_u32(dsm);
    const uint32_t offAH = 0, offAL = TILEB;
    const uint32_t offWh = 2 * TILEB, offWl = 2 * TILEB + K1WT;

    int tid = threadIdx.x;
    int widx = tid >> 5, lane = tid & 31;
    int rb = widx >> 1;      // row block 0..3
    int cb = widx & 1;       // col block 0..1 (32 cols each)
    int row0 = blockIdx.x * 128;

    float acc[8][4];         // [rt*4 + tp*2 + j][quad]
#pragma unroll
    for (int t = 0; t < 8; t++)
#pragma unroll
        for (int q = 0; q < 4; q++) acc[t][q] = 0.f;

    uint32_t aRowL = (uint32_t)(lane & 15);
    uint32_t aK8   = (uint32_t)((lane >> 4) * 8);
    uint32_t wN    = (uint32_t)((lane >> 4) * 8 + (lane & 7));
    uint32_t wK8   = (uint32_t)(((lane >> 3) & 1) * 8);

    auto cp_w = [&](int c) {
        const char* hsrc = (const char*)(Wh + (size_t)c * K1CH);
        const char* lsrc = (const char*)(Wl + (size_t)c * K1CH);
        for (uint32_t i = tid * 16; i < K1WT; i += 256 * 16) {
            cp_async16(smBase + offWh + i, hsrc + i);
            cp_async16(smBase + offWl + i, lsrc + i);
        }
        cp_commit();
    };

#pragma unroll 1
    for (int c = 0; c < 9; c++) {
        cp_w(c);
        // --- fill A tile ---
        int r = tid >> 1;
        int half = tid & 1;
        int gr = row0 + r;
        char* pH = dsm + offAH + (uint32_t)r * 272u;
        char* pL = dsm + offAL + (uint32_t)r * 272u;
        if (c < 8) {
            // 8 features per thread: f = 16c + half*8 + j; cols (half*8+j)*6 + tt
            int f0 = c * 16 + half * 8;
            float xv[8];
            if (gr < M) {
                float4 xa = *reinterpret_cast<const float4*>(x + (size_t)gr * 128 + f0);
                float4 xb = *reinterpret_cast<const float4*>(x + (size_t)gr * 128 + f0 + 4);
                xv[0] = xa.x; xv[1] = xa.y; xv[2] = xa.z; xv[3] = xa.w;
                xv[4] = xb.x; xv[5] = xb.y; xv[6] = xb.z; xv[7] = xb.w;
            } else {
#pragma unroll
                for (int j = 0; j < 8; j++) xv[j] = 0.f;
            }
#pragma unroll
            for (int j = 0; j < 8; j++) {
                float b[8];
                bspline8(xv[j], b);
                int col = (half * 8 + j) * 6;   // even -> u32-aligned
                __nv_bfloat16 h0, h1, h2, h3, h4, h5, l0, l1, l2, l3, l4, l5;
                split2(b[2], h0, l0); split2(b[3], h1, l1);
                split2(b[4], h2, l2); split2(b[5], h3, l3);
                split2(b[6], h4, l4); split2(b[7], h5, l5);
                *(uint32_t*)(pH + col * 2)     = pack_bf16(h0, h1);
                *(uint32_t*)(pH + col * 2 + 4) = pack_bf16(h2, h3);
                *(uint32_t*)(pH + col * 2 + 8) = pack_bf16(h4, h5);
                *(uint32_t*)(pL + col * 2)     = pack_bf16(l0, l1);
                *(uint32_t*)(pL + col * 2 + 4) = pack_bf16(l2, l3);
                *(uint32_t*)(pL + col * 2 + 8) = pack_bf16(l4, l5);
            }
        } else {
            // base chunk: silu(x), 64 cols per thread-half
            int c0 = half * 64;
            const float* Arow = x + (size_t)gr * 128;
            for (int cc = c0; cc < c0 + 64; cc += 4) {
                float4 a = make_float4(0.f, 0.f, 0.f, 0.f);
                if (gr < M) a = *reinterpret_cast<const float4*>(Arow + cc);
                float v0 = silu(a.x), v1 = silu(a.y), v2 = silu(a.z), v3 = silu(a.w);
                __nv_bfloat16 h0, h1, h2, h3, l0, l1, l2, l3;
                split2(v0, h0, l0); split2(v1, h1, l1);
                split2(v2, h2, l2); split2(v3, h3, l3);
                *(uint32_t*)(pH + cc * 2)     = pack_bf16(h0, h1);
                *(uint32_t*)(pH + cc * 2 + 4) = pack_bf16(h2, h3);
                *(uint32_t*)(pL + cc * 2)     = pack_bf16(l0, l1);
                *(uint32_t*)(pL + cc * 2 + 4) = pack_bf16(l2, l3);
            }
        }
        cp_wait_all();
        __syncthreads();

        int ksteps = (c < 8) ? 6 : 8;
#pragma unroll 1
        for (int ks = 0; ks < ksteps; ks++) {
            uint32_t kb = (uint32_t)(ks * 16);
            uint32_t ah[2][4], al[2][4];
#pragma unroll
            for (int rt = 0; rt < 2; rt++) {
                uint32_t aoff = (((uint32_t)(rb * 32 + rt * 16) + aRowL) * WSTRIDE + kb + aK8) * 2;
                ldsm_x4(ah[rt], smBase + offAH + aoff);
                ldsm_x4(al[rt], smBase + offAL + aoff);
            }
            uint32_t bh[2][4], bl[2][4];
#pragma unroll
            for (int tp = 0; tp < 2; tp++) {
                uint32_t woff = (((uint32_t)(cb * 32 + tp * 16) + wN) * WSTRIDE + kb + wK8) * 2;
                ldsm_x4(bh[tp], smBase + offWh + woff);
                ldsm_x4(bl[tp], smBase + offWl + woff);
            }
#pragma unroll
            for (int rt = 0; rt < 2; rt++) {
#pragma unroll
                for (int tp = 0; tp < 2; tp++) {
                    int t0 = rt * 4 + tp * 2;
                    mma_bf16(acc[t0],     ah[rt], bh[tp][0], bh[tp][1]);
                    mma_bf16(acc[t0],     ah[rt], bl[tp][0], bl[tp][1]);
                    mma_bf16(acc[t0],     al[rt], bh[tp][0], bh[tp][1]);
                    mma_bf16(acc[t0 + 1], ah[rt], bh[tp][2], bh[tp][3]);
                    mma_bf16(acc[t0 + 1], ah[rt], bl[tp][2], bl[tp][3]);
                    mma_bf16(acc[t0 + 1], al[rt], bh[tp][2], bh[tp][3]);
                }
            }
        }
        __syncthreads();   // A/W tiles reused next chunk
    }

    // epilogue: no bias, no relu
#pragma unroll
    for (int rt = 0; rt < 2; rt++) {
        int gr0 = row0 + rb * 32 + rt * 16 + (lane >> 2);
        int gr1 = gr0 + 8;
#pragma unroll
        for (int tp = 0; tp < 2; tp++) {
#pragma unroll
            for (int j = 0; j < 2; j++) {
                int col = cb * 32 + tp * 16 + j * 8 + (lane & 3) * 2;
                float* a = acc[rt * 4 + tp * 2 + j];
                if (gr0 < M) *reinterpret_cast<float2*>(out + (size_t)gr0 * 64 + col) = make_float2(a[0], a[1]);
                if (gr1 < M) *reinterpret_cast<float2*>(out + (size_t)gr1 * 64 + col) = make_float2(a[2], a[3]);
            }
        }
    }
}

// ---------------- KAN layer 2 (unchanged) ----------------------------------------
__global__ void kan2_kernel(const float* __restrict__ hin,
                            const float* __restrict__ spline,
                            const float* __restrict__ scaler,
                            const float* __restrict__ basew,
                            float* __restrict__ out, int M)
{
    __shared__ float sh[128][65];
    __shared__ float sw[2][64][8];
    __shared__ float sb[2][64];
    int tid = threadIdx.x;
    int row0 = blockIdx.x * 128;
    for (int idx = tid; idx < 1024; idx += 128) {
        int o = idx >> 9, rem = idx & 511, f = rem >> 3, t = rem & 7;
        sw[o][f][t] = spline[idx] * scaler[o * 64 + f];
    }
    if (tid < 128) sb[tid >> 6][tid & 63] = basew[tid];
    for (int idx = tid; idx < 128 * 64; idx += 128) {
        int r = idx >> 6, f = idx & 63;
        int gr = row0 + r;
        sh[r][f] = (gr < M) ? hin[(size_t)gr * 64 + f] : 0.f;
    }
    __syncthreads();
    int gr = row0 + tid;
    if (gr >= M) return;
    float acc0 = 0.f, acc1 = 0.f;
    for (int f = 0; f < 64; f++) {
        float xv = sh[tid][f];
        float s = silu(xv);
        acc0 += s * sb[0][f];
        acc1 += s * sb[1][f];
        float b[8];
        bspline8(xv, b);
#pragma unroll
        for (int t = 0; t < 8; t++) {
            acc0 += b[t] * sw[0][f][t];
            acc1 += b[t] * sw[1][f][t];
        }
    }
    out[(size_t)gr * 2 + 0] = acc0;
    out[(size_t)gr * 2 + 1] = acc1;
}

// ---------------- launch ----------------
extern "C" void kernel_launch(void* const* d_in, const int* in_sizes, int n_in,
                              void* d_out, int out_size)
{
    const float* x_email    = (const float*)d_in[0];
    const int*   ei_ue      = (const int*)d_in[1];
    const int*   ei_eu      = (const int*)d_in[2];
    const float* w_email    = (const float*)d_in[3];
    const float* b_email    = (const float*)d_in[4];
    const float* emb_user   = (const float*)d_in[5];
    const float* w_l1_ue_n  = (const float*)d_in[6];
    const float* b_l1_ue    = (const float*)d_in[7];
    const float* w_l1_ue_r  = (const float*)d_in[8];
    const float* w_l1_eu_n  = (const float*)d_in[9];
    const float* b_l1_eu    = (const float*)d_in[10];
    const float* w_l1_eu_r  = (const float*)d_in[11];
    const float* w_l2_ue_n  = (const float*)d_in[12];
    const float* b_l2_ue    = (const float*)d_in[13];
    const float* w_l2_ue_r  = (const float*)d_in[14];
    const float* kan1_base   = (const float*)d_in[18];
    const float* kan1_spline = (const float*)d_in[19];
    const float* kan1_scaler = (const float*)d_in[20];
    const float* kan2_base   = (const float*)d_in[22];
    const float* kan2_spline = (const float*)d_in[23];
    const float* kan2_scaler = (const float*)d_in[24];
    float* out = (float*)d_out;

    float *xe, *accE, *accE2, *e1, *accUx, *u1, *hbuf, *cntE, *cntU, *bias1, *gb2;
    cudaGetSymbolAddress((void**)&xe,    g_xe);
    cudaGetSymbolAddress((void**)&accE,  g_accE);
    cudaGetSymbolAddress((void**)&accE2, g_accE2);
    cudaGetSymbolAddress((void**)&e1,    g_e1);
    cudaGetSymbolAddress((void**)&accUx, g_accUx);
    cudaGetSymbolAddress((void**)&u1,    g_u1);
    cudaGetSymbolAddress((void**)&hbuf,  g_h);
    cudaGetSymbolAddress((void**)&cntE,  g_cntE);
    cudaGetSymbolAddress((void**)&cntU,  g_cntU);
    cudaGetSymbolAddress((void**)&bias1, g_bias1);
    cudaGetSymbolAddress((void**)&gb2,   g_gb2);
    __nv_bfloat16 *wh, *wl, *wch, *wcl, *k1wh, *k1wl;
    cudaGetSymbolAddress((void**)&wh,   g_wh);
    cudaGetSymbolAddress((void**)&wl,   g_wl);
    cudaGetSymbolAddress((void**)&wch,  g_wch);
    cudaGetSymbolAddress((void**)&wcl,  g_wcl);
    cudaGetSymbolAddress((void**)&k1wh, g_k1wh);
    cudaGetSymbolAddress((void**)&k1wl, g_k1wl);
    auto WH = [&](int m) { return wh + (size_t)m * 128 * WSTRIDE; };
    auto WL = [&](int m) { return wl + (size_t)m * 128 * WSTRIDE; };
    auto WCH = [&](int m) { return wch + (size_t)m * 128 * WSTRIDE; };
    auto WCL = [&](int m) { return wcl + (size_t)m * 128 * WSTRIDE; };

    const int gE = (NE + 127) / 128;   // 1563
    const int gU = (NU + 127) / 128;   // 782
    const int gScat = (NEDGE / 8 * 32 + 255) / 256;    // 15625
    const int gScat64 = (NEDGE / 16 * 32 + 255) / 256; // 7813

    const int SMEM_TC = (int)(6 * TILEB);
    const int SMEM_K1 = (int)(2 * TILEB + 2 * K1WT);   // 104448
    cudaFuncSetAttribute(gemm_tc, cudaFuncAttributeMaxDynamicSharedMemorySize, SMEM_TC);
    cudaFuncSetAttribute(kan1_tc, cudaFuncAttributeMaxDynamicSharedMemorySize, SMEM_K1);

    // 0: init
    init_kernel<<<4096, 256>>>(w_email, b_email, w_l1_ue_n, w_l1_ue_r, b_l1_ue,
                               w_l1_eu_n, w_l1_eu_r, w_l2_ue_n, w_l2_ue_r,
                               kan1_spline, kan1_scaler, kan1_base);
    // 1: conv1 email aggregate
    scatter_kernel<<<gScat, 256>>>(ei_ue, ei_ue + NEDGE, emb_user, accE, cntE, 1);
    // 2: conv1 user aggregate (x_email 64-dim)
    scatter64_kernel<<<gScat64, 256>>>(ei_eu, ei_eu + NEDGE, x_email, accUx, cntU);
    // 3: conv1 email combine
    gemm_tc<<<gE, 256, SMEM_TC>>>(accE, 128, WH(0), WL(0),
                                  x_email, 64, WCH(0), WCL(0),
                                  bias1, cntE, nullptr, e1, NE);
    // 4: conv1 user combine
    gemm_tc<<<gU, 256, SMEM_TC>>>(accUx, 64, WCH(1), WCL(1),
                                  emb_user, 128, WH(3), WL(3),
                                  b_l1_eu, cntU, gb2, u1, NU);
    // 5: conv2 email aggregate
    scatter_kernel<<<gScat, 256>>>(ei_ue, ei_ue + NEDGE, u1, accE2, nullptr, 0);
    // 6: conv2 email combine
    gemm_tc<<<gE, 256, SMEM_TC>>>(accE2, 128, WH(4), WL(4),
                                  e1, 128, WH(5), WL(5),
                                  b_l2_ue, cntE, nullptr, xe /*= e2*/, NE);
    // 7: KAN layer 1 (tensor cores, 6 bases)
    kan1_tc<<<gE, 256, SMEM_K1>>>(xe, k1wh, k1wl, hbuf, NE);
    // 8: KAN layer 2
    kan2_kernel<<<gE, 128>>>(hbuf, kan2_spline, kan2_scaler, kan2_base, out, NE);
}

// round 17
// speedup vs baseline: 1.4579x; 1.0005x over previous
#include <cuda_runtime.h>
#include <cuda_bf16.h>
#include <math.h>
#include <stdint.h>

#define NE 200000
#define NU 100000
#define NEDGE 1000000
#define HDIM 128

// ---------------- scratch (static device arrays; no allocation) ----------------
__device__ float g_xe[(size_t)NE * HDIM];     // e2 lives here
__device__ float g_accE[(size_t)NE * HDIM];
__device__ float g_accE2[(size_t)NE * HDIM];
__device__ float g_e1[(size_t)NE * HDIM];
__device__ float g_accUx[(size_t)NU * 64];    // x_email aggregated (64-dim)
__device__ float g_u1[(size_t)NU * HDIM];
__device__ float g_h[(size_t)NE * 64];
__device__ float g_cntE[NE];
__device__ float g_cntU[NU];
__device__ float g_bias1[128];                // b_l1_ue + W1r@b_email
__device__ float g_gb2[128];                  // W2n@b_email (gated by cntU>0)
// bf16 hi/lo weight tiles, padded row stride 136 (272B -> conflict-free ldmatrix)
#define WSTRIDE 136
__device__ __align__(16) __nv_bfloat16 g_wh[6][128 * WSTRIDE];
__device__ __align__(16) __nv_bfloat16 g_wl[6][128 * WSTRIDE];
__device__ __align__(16) __nv_bfloat16 g_wch[2][128 * WSTRIDE];  // composites (K=64)
__device__ __align__(16) __nv_bfloat16 g_wcl[2][128 * WSTRIDE];
// kan1 weight chunks: [9][64][136]; c<8: spline*scaler (16 feats x 6 bases), c=8: base_w
#define K1CH 8704   // 64*136
__device__ __align__(16) __nv_bfloat16 g_k1wh[9 * K1CH];
__device__ __align__(16) __nv_bfloat16 g_k1wl[9 * K1CH];

// ---------------- helpers ----------------
__device__ __forceinline__ uint32_t smem_u32(const void* p) {
    return (uint32_t)__cvta_generic_to_shared(p);
}
__device__ __forceinline__ void cp_async16(uint32_t dst, const void* src) {
    asm volatile("cp.async.ca.shared.global [%0], [%1], 16;" :: "r"(dst), "l"(src));
}
__device__ __forceinline__ void cp_commit() { asm volatile("cp.async.commit_group;"); }
__device__ __forceinline__ void cp_wait_all() {
    asm volatile("cp.async.wait_group 0;" ::: "memory");
}
__device__ __forceinline__ uint32_t pack_bf16(__nv_bfloat16 a, __nv_bfloat16 b) {
    uint16_t ua = *(uint16_t*)&a, ub = *(uint16_t*)&b;
    return (uint32_t)ua | ((uint32_t)ub << 16);
}
__device__ __forceinline__ void ldsm_x4(uint32_t r[4], uint32_t addr) {
    asm volatile("ldmatrix.sync.aligned.m8n8.x4.shared.b16 {%0,%1,%2,%3}, [%4];"
                 : "=r"(r[0]), "=r"(r[1]), "=r"(r[2]), "=r"(r[3]) : "r"(addr));
}
__device__ __forceinline__ void mma_bf16(float d[4], const uint32_t a[4],
                                         uint32_t b0, uint32_t b1) {
    asm volatile(
        "mma.sync.aligned.m16n8k16.row.col.f32.bf16.bf16.f32 "
        "{%0,%1,%2,%3}, {%4,%5,%6,%7}, {%8,%9}, {%0,%1,%2,%3};"
        : "+f"(d[0]), "+f"(d[1]), "+f"(d[2]), "+f"(d[3])
        : "r"(a[0]), "r"(a[1]), "r"(a[2]), "r"(a[3]), "r"(b0), "r"(b1));
}
__device__ __forceinline__ void split_store(float w, __nv_bfloat16* ph, __nv_bfloat16* pl) {
    __nv_bfloat16 h = __float2bfloat16(w);
    __nv_bfloat16 l = __float2bfloat16(w - __bfloat162float(h));
    *ph = h; *pl = l;
}
__device__ __forceinline__ void split2(float v, __nv_bfloat16& h, __nv_bfloat16& l) {
    h = __float2bfloat16(v);
    l = __float2bfloat16(v - __bfloat162float(h));
}
// f32x2 packed helpers (kan2)
__device__ __forceinline__ void fma_x2(unsigned long long& acc, unsigned long long a,
                                       unsigned long long b) {
    asm("fma.rn.f32x2 %0, %1, %2, %0;" : "+l"(acc) : "l"(a), "l"(b));
}
__device__ __forceinline__ unsigned long long dup_x2(float v) {
    unsigned long long r;
    asm("mov.b64 %0, {%1, %1};" : "=l"(r) : "f"(v));
    return r;
}
__device__ __forceinline__ unsigned long long pack_x2(float lo, float hi) {
    unsigned long long r;
    asm("mov.b64 %0, {%1, %2};" : "=l"(r) : "f"(lo), "f"(hi));
    return r;
}
__device__ __forceinline__ void unpack_x2(unsigned long long v, float& lo, float& hi) {
    asm("mov.b64 {%0, %1}, %2;" : "=f"(lo), "=f"(hi) : "l"(v));
}

// ---------------- B-spline bases (uniform grid, grid_size=5, k=3 -> 8 bases) ----
__device__ __forceinline__ void bspline8(float x, float b[8]) {
    const float hstep = 2.0f / 5.0f;
    float g[12];
#pragma unroll
    for (int t = 0; t < 12; t++) g[t] = (float)(t - 3) * hstep - 1.0f;
    float p0[11], p1[10], p2[9];
#pragma unroll
    for (int t = 0; t < 11; t++) p0[t] = (x >= g[t] && x < g[t + 1]) ? 1.0f : 0.0f;
#pragma unroll
    for (int t = 0; t < 10; t++)
        p1[t] = ((x - g[t]) * (1.0f / (g[t + 1] - g[t]))) * p0[t]
              + ((g[t + 2] - x) * (1.0f / (g[t + 2] - g[t + 1]))) * p0[t + 1];
#pragma unroll
    for (int t = 0; t < 9; t++)
        p2[t] = ((x - g[t]) * (1.0f / (g[t + 2] - g[t]))) * p1[t]
              + ((g[t + 3] - x) * (1.0f / (g[t + 3] - g[t + 1]))) * p1[t + 1];
#pragma unroll
    for (int t = 0; t < 8; t++)
        b[t] = ((x - g[t]) * (1.0f / (g[t + 3] - g[t]))) * p2[t]
             + ((g[t + 4] - x) * (1.0f / (g[t + 4] - g[t + 1]))) * p2[t + 1];
}

__device__ __forceinline__ float silu(float x) {
    return x / (1.0f + __expf(-x));
}

// ---------------- init: zero accum + split weights + composites + kan1 chunks ----
__global__ void init_kernel(const float* we, const float* be,
                            const float* w1n, const float* w1r, const float* b1,
                            const float* w2n, const float* w2r,
                            const float* w3n, const float* w3r,
                            const float* k1spline, const float* k1scaler,
                            const float* k1base)
{
    int i = blockIdx.x * blockDim.x + threadIdx.x;
    int stride = gridDim.x * blockDim.x;
    const int nE4 = NE * HDIM / 4;
    const int nUx4 = NU * 64 / 4;
    const int cE4 = NE / 4, cU4 = NU / 4;
    float4 z = make_float4(0.f, 0.f, 0.f, 0.f);
    float4* aE  = (float4*)g_accE;
    float4* aE2 = (float4*)g_accE2;
    for (int k = i; k < nE4; k += stride) { aE[k] = z; aE2[k] = z; }
    for (int k = i; k < nUx4; k += stride) ((float4*)g_accUx)[k] = z;
    for (int k = i; k < cE4; k += stride) ((float4*)g_cntE)[k] = z;
    for (int k = i; k < cU4; k += stride) ((float4*)g_cntU)[k] = z;
    for (int k = i; k < 6 * 128 * 128; k += stride) {
        int m = k >> 14, r = k & 16383;
        int n = r >> 7, c = r & 127;
        const float* src;
        switch (m) {
            case 0: src = w1n; break;
            case 1: src = w1r; break;
            case 2: src = w2n; break;
            case 3: src = w2r; break;
            case 4: src = w3n; break;
            default: src = w3r; break;
        }
        split_store(src[n * 128 + c], &g_wh[m][n * WSTRIDE + c], &g_wl[m][n * WSTRIDE + c]);
    }
    for (int k = i; k < 2 * 128 * 64; k += stride) {
        int m = k >> 13, r = k & 8191;
        int n = r >> 6, c = r & 63;
        const float* Wr = m ? w2n : w1r;
        float s = 0.f;
#pragma unroll 4
        for (int j = 0; j < 128; j++) s += Wr[n * 128 + j] * we[j * 64 + c];
        split_store(s, &g_wch[m][n * WSTRIDE + c], &g_wcl[m][n * WSTRIDE + c]);
    }
    for (int k = i; k < 2 * 128; k += stride) {
        int m = k >> 7, n = k & 127;
        const float* Wr = m ? w2n : w1r;
        float s = 0.f;
#pragma unroll 4
        for (int j = 0; j < 128; j++) s += Wr[n * 128 + j] * be[j];
        if (m == 0) g_bias1[n] = b1[n] + s;
        else        g_gb2[n] = s;
    }
    for (int k = i; k < 9 * K1CH; k += stride) {
        int c = k / K1CH, r = k % K1CH;
        int n = r / 136, col = r % 136;
        float w = 0.f;
        if (c < 8) {
            if (col < 96) {
                int f = 16 * c + col / 6, tt = col % 6;
                w = k1spline[(size_t)n * 1024 + f * 8 + tt + 2] * k1scaler[n * 128 + f];
            }
        } else {
            if (col < 128) w = k1base[n * 128 + col];
        }
        split_store(w, &g_k1wh[k], &g_k1wl[k]);
    }
}

// ---------------- edge scatter (128-dim): one warp per 8 edges, vector RED ------
__global__ void scatter_kernel(const int* __restrict__ src, const int* __restrict__ dst,
                               const float* __restrict__ xsrc,
                               float* __restrict__ accum, float* __restrict__ cnt,
                               int doCnt)
{
    int warp = (blockIdx.x * blockDim.x + threadIdx.x) >> 5;
    int lane = threadIdx.x & 31;
    int e0 = warp * 8;
    if (e0 >= NEDGE) return;
    int4 sa = *reinterpret_cast<const int4*>(src + e0);
    int4 sb = *reinterpret_cast<const int4*>(src + e0 + 4);
    int4 da = *reinterpret_cast<const int4*>(dst + e0);
    int4 db = *reinterpret_cast<const int4*>(dst + e0 + 4);
    int s[8] = {sa.x, sa.y, sa.z, sa.w, sb.x, sb.y, sb.z, sb.w};
    int d[8] = {da.x, da.y, da.z, da.w, db.x, db.y, db.z, db.w};
    float4 v[8];
#pragma unroll
    for (int i = 0; i < 8; i++)
        v[i] = *reinterpret_cast<const float4*>(xsrc + (size_t)s[i] * HDIM + lane * 4);
#pragma unroll
    for (int i = 0; i < 8; i++) {
        float* a = accum + (size_t)d[i] * HDIM + lane * 4;
        asm volatile("red.global.add.v4.f32 [%0], {%1, %2, %3, %4};"
                     :: "l"(a), "f"(v[i].x), "f"(v[i].y), "f"(v[i].z), "f"(v[i].w) : "memory");
    }
    if (doCnt && lane == 0) {
#pragma unroll
        for (int i = 0; i < 8; i++) {
            float one = 1.0f;
            asm volatile("red.global.add.f32 [%0], %1;" :: "l"(cnt + d[i]), "f"(one) : "memory");
        }
    }
}

// ---------------- edge scatter (64-dim): each half-warp handles 8 edges ---------
__global__ void scatter64_kernel(const int* __restrict__ src, const int* __restrict__ dst,
                                 const float* __restrict__ xsrc,
                                 float* __restrict__ accum,
                                 float* __restrict__ cnt)
{
    int warp = (blockIdx.x * blockDim.x + threadIdx.x) >> 5;
    int lane = threadIdx.x & 31;
    int half = lane >> 4, sub = lane & 15;
    int e0 = warp * 16 + half * 8;
    if (e0 >= NEDGE) return;
    int4 sa = *reinterpret_cast<const int4*>(src + e0);
    int4 sb = *reinterpret_cast<const int4*>(src + e0 + 4);
    int4 da = *reinterpret_cast<const int4*>(dst + e0);
    int4 db = *reinterpret_cast<const int4*>(dst + e0 + 4);
    int s[8] = {sa.x, sa.y, sa.z, sa.w, sb.x, sb.y, sb.z, sb.w};
    int d[8] = {da.x, da.y, da.z, da.w, db.x, db.y, db.z, db.w};
    float4 v[8];
#pragma unroll
    for (int i = 0; i < 8; i++)
        v[i] = *reinterpret_cast<const float4*>(xsrc + (size_t)s[i] * 64 + sub * 4);
#pragma unroll
    for (int i = 0; i < 8; i++) {
        float* a = accum + (size_t)d[i] * 64 + sub * 4;
        asm volatile("red.global.add.v4.f32 [%0], {%1, %2, %3, %4};"
                     :: "l"(a), "f"(v[i].x), "f"(v[i].y), "f"(v[i].z), "f"(v[i].w) : "memory");
    }
    if (sub == 0) {
#pragma unroll
        for (int i = 0; i < 8; i++) {
            float one = 1.0f;
            asm volatile("red.global.add.f32 [%0], %1;" :: "l"(cnt + d[i]), "f"(one) : "memory");
        }
    }
}

// ---------------- tensor-core combine GEMM (MMA product-major reorder) -----------
#define TILEB 34816u
__global__ void __launch_bounds__(256)
gemm_tc(const float* __restrict__ A1, int K1,
        const __nv_bfloat16* __restrict__ W1h, const __nv_bfloat16* __restrict__ W1l,
        const float* __restrict__ A2, int K2,
        const __nv_bfloat16* __restrict__ W2h, const __nv_bfloat16* __restrict__ W2l,
        const float* __restrict__ bias, const float* __restrict__ cnt,
        const float* __restrict__ gbias,
        float* __restrict__ out, int M)
{
    extern __shared__ char dsm[];
    uint32_t smBase = smem_u32(dsm);
    const uint32_t offAH = 0, offAL = TILEB;
    const uint32_t offW1h = 2 * TILEB, offW1l = 3 * TILEB;
    const uint32_t offW2h = 4 * TILEB, offW2l = 5 * TILEB;

    int tid = threadIdx.x;
    int widx = tid >> 5, lane = tid & 31;
    int rb = widx >> 1;
    int cb = widx & 1;
    int row0 = blockIdx.x * 128;

    {
        for (uint32_t i = tid * 16; i < TILEB; i += 256 * 16) {
            cp_async16(smBase + offW1h + i, (const char*)W1h + i);
            cp_async16(smBase + offW1l + i, (const char*)W1l + i);
            cp_async16(smBase + offW2h + i, (const char*)W2h + i);
            cp_async16(smBase + offW2l + i, (const char*)W2l + i);
        }
        cp_commit();
    }

    auto convA = [&](const float* A, int K, bool mean) {
        int r = tid >> 1;
        int half = tid & 1;
        int cw = K >> 1;
        int c0 = half * cw;
        int gr = row0 + r;
        float inv = 1.f;
        if (mean) {
            float cv = (gr < M) ? cnt[gr] : 1.f;
            inv = 1.f / fmaxf(cv, 1.f);
        }
        const float* Arow = A + (size_t)gr * K;
        char* pH = dsm + offAH + (uint32_t)r * 272u;
        char* pL = dsm + offAL + (uint32_t)r * 272u;
        for (int c = c0; c < c0 + cw; c += 4) {
            float4 a = make_float4(0.f, 0.f, 0.f, 0.f);
            if (gr < M) a = *reinterpret_cast<const float4*>(Arow + c);
            float v0 = a.x * inv, v1 = a.y * inv, v2 = a.z * inv, v3 = a.w * inv;
            __nv_bfloat16 h0, h1, h2, h3, l0, l1, l2, l3;
            split2(v0, h0, l0); split2(v1, h1, l1);
            split2(v2, h2, l2); split2(v3, h3, l3);
            *(uint32_t*)(pH + c * 2)     = pack_bf16(h0, h1);
            *(uint32_t*)(pH + c * 2 + 4) = pack_bf16(h2, h3);
            *(uint32_t*)(pL + c * 2)     = pack_bf16(l0, l1);
            *(uint32_t*)(pL + c * 2 + 4) = pack_bf16(l2, l3);
        }
    };

    float acc[16][4];
#pragma unroll
    for (int t = 0; t < 16; t++)
#pragma unroll
        for (int q = 0; q < 4; q++) acc[t][q] = 0.f;

    uint32_t aRowL = (uint32_t)(lane & 15);
    uint32_t aK8   = (uint32_t)((lane >> 4) * 8);
    uint32_t wN    = (uint32_t)((lane >> 4) * 8 + (lane & 7));
    uint32_t wK8   = (uint32_t)(((lane >> 3) & 1) * 8);

    for (int ph = 0; ph < 2; ph++) {
        const float* A = ph ? A2 : A1;
        int K = ph ? K2 : K1;
        uint32_t offh = ph ? offW2h : offW1h;
        uint32_t offl = ph ? offW2l : offW1l;
        if (ph) __syncthreads();
        convA(A, K, ph == 0);
        if (ph == 0) cp_wait_all();
        __syncthreads();

        int ksteps = K >> 4;
#pragma unroll 1
        for (int ks = 0; ks < ksteps; ks++) {
            uint32_t kb = (uint32_t)(ks * 16);
            uint32_t ah[2][4], al[2][4];
#pragma unroll
            for (int rt = 0; rt < 2; rt++) {
                uint32_t aoff = (((uint32_t)(rb * 32 + rt * 16) + aRowL) * WSTRIDE + kb + aK8) * 2;
                ldsm_x4(ah[rt], smBase + offAH + aoff);
                ldsm_x4(al[rt], smBase + offAL + aoff);
            }
            uint32_t bh[4][4], bl[4][4];
#pragma unroll
            for (int tp = 0; tp < 4; tp++) {
                uint32_t woff = (((uint32_t)(cb * 64 + tp * 16) + wN) * WSTRIDE + kb + wK8) * 2;
                ldsm_x4(bh[tp], smBase + offh + woff);
                ldsm_x4(bl[tp], smBase + offl + woff);
            }
            // product-major MMA order: same-acc reuse distance = 16 (no RAW stalls)
#pragma unroll
            for (int rt = 0; rt < 2; rt++)
#pragma unroll
                for (int tp = 0; tp < 4; tp++) {
                    int t0 = rt * 8 + tp * 2;
                    mma_bf16(acc[t0],     ah[rt], bh[tp][0], bh[tp][1]);
                    mma_bf16(acc[t0 + 1], ah[rt], bh[tp][2], bh[tp][3]);
                }
#pragma unroll
            for (int rt = 0; rt < 2; rt++)
#pragma unroll
                for (int tp = 0; tp < 4; tp++) {
                    int t0 = rt * 8 + tp * 2;
                    mma_bf16(acc[t0],     ah[rt], bl[tp][0], bl[tp][1]);
                    mma_bf16(acc[t0 + 1], ah[rt], bl[tp][2], bl[tp][3]);
                }
#pragma unroll
            for (int rt = 0; rt < 2; rt++)
#pragma unroll
                for (int tp = 0; tp < 4; tp++) {
                    int t0 = rt * 8 + tp * 2;
                    mma_bf16(acc[t0],     al[rt], bh[tp][0], bh[tp][1]);
                    mma_bf16(acc[t0 + 1], al[rt], bh[tp][2], bh[tp][3]);
                }
        }
    }

#pragma unroll
    for (int rt = 0; rt < 2; rt++) {
        int gr0 = row0 + rb * 32 + rt * 16 + (lane >> 2);
        int gr1 = gr0 + 8;
        float gf0 = 0.f, gf1 = 0.f;
        if (gbias) {
            gf0 = (gr0 < M && cnt[gr0] > 0.5f) ? 1.f : 0.f;
            gf1 = (gr1 < M && cnt[gr1] > 0.5f) ? 1.f : 0.f;
        }
#pragma unroll
        for (int j = 0; j < 8; j++) {
            int col = cb * 64 + j * 8 + (lane & 3) * 2;
            float b0 = bias[col], b1 = bias[col + 1];
            float g0 = 0.f, g1 = 0.f;
            if (gbias) { g0 = gbias[col]; g1 = gbias[col + 1]; }
            float* a = acc[rt * 8 + j];
            float d0 = fmaxf(a[0] + b0 + g0 * gf0, 0.f);
            float d1 = fmaxf(a[1] + b1 + g1 * gf0, 0.f);
            float d2 = fmaxf(a[2] + b0 + g0 * gf1, 0.f);
            float d3 = fmaxf(a[3] + b1 + g1 * gf1, 0.f);
            if (gr0 < M) *reinterpret_cast<float2*>(out + (size_t)gr0 * 128 + col) = make_float2(d0, d1);
            if (gr1 < M) *reinterpret_cast<float2*>(out + (size_t)gr1 * 128 + col) = make_float2(d2, d3);
        }
    }
}

// ---------------- KAN layer 1: tensor-core, 6-basis, product-major MMA -----------
#define K1WT 17408u
__global__ void __launch_bounds__(256, 2)
kan1_tc(const float* __restrict__ x,
        const __nv_bfloat16* __restrict__ Wh,
        const __nv_bfloat16* __restrict__ Wl,
        float* __restrict__ out, int M)
{
    extern __shared__ char dsm[];
    uint32_t smBase = smem_u32(dsm);
    const uint32_t offAH = 0, offAL = TILEB;
    const uint32_t offWh = 2 * TILEB, offWl = 2 * TILEB + K1WT;

    int tid = threadIdx.x;
    int widx = tid >> 5, lane = tid & 31;
    int rb = widx >> 1;
    int cb = widx & 1;
    int row0 = blockIdx.x * 128;

    float acc[8][4];
#pragma unroll
    for (int t = 0; t < 8; t++)
#pragma unroll
        for (int q = 0; q < 4; q++) acc[t][q] = 0.f;

    uint32_t aRowL = (uint32_t)(lane & 15);
    uint32_t aK8   = (uint32_t)((lane >> 4) * 8);
    uint32_t wN    = (uint32_t)((lane >> 4) * 8 + (lane & 7));
    uint32_t wK8   = (uint32_t)(((lane >> 3) & 1) * 8);

    auto cp_w = [&](int c) {
        const char* hsrc = (const char*)(Wh + (size_t)c * K1CH);
        const char* lsrc = (const char*)(Wl + (size_t)c * K1CH);
        for (uint32_t i = tid * 16; i < K1WT; i += 256 * 16) {
            cp_async16(smBase + offWh + i, hsrc + i);
            cp_async16(smBase + offWl + i, lsrc + i);
        }
        cp_commit();
    };

#pragma unroll 1
    for (int c = 0; c < 9; c++) {
        cp_w(c);
        int r = tid >> 1;
        int half = tid & 1;
        int gr = row0 + r;
        char* pH = dsm + offAH + (uint32_t)r * 272u;
        char* pL = dsm + offAL + (uint32_t)r * 272u;
        if (c < 8) {
            int f0 = c * 16 + half * 8;
            float xv[8];
            if (gr < M) {
                float4 xa = *reinterpret_cast<const float4*>(x + (size_t)gr * 128 + f0);
                float4 xb = *reinterpret_cast<const float4*>(x + (size_t)gr * 128 + f0 + 4);
                xv[0] = xa.x; xv[1] = xa.y; xv[2] = xa.z; xv[3] = xa.w;
                xv[4] = xb.x; xv[5] = xb.y; xv[6] = xb.z; xv[7] = xb.w;
            } else {
#pragma unroll
                for (int j = 0; j < 8; j++) xv[j] = 0.f;
            }
#pragma unroll
            for (int j = 0; j < 8; j++) {
                float b[8];
                bspline8(xv[j], b);
                int col = (half * 8 + j) * 6;
                __nv_bfloat16 h0, h1, h2, h3, h4, h5, l0, l1, l2, l3, l4, l5;
                split2(b[2], h0, l0); split2(b[3], h1, l1);
                split2(b[4], h2, l2); split2(b[5], h3, l3);
                split2(b[6], h4, l4); split2(b[7], h5, l5);
                *(uint32_t*)(pH + col * 2)     = pack_bf16(h0, h1);
                *(uint32_t*)(pH + col * 2 + 4) = pack_bf16(h2, h3);
                *(uint32_t*)(pH + col * 2 + 8) = pack_bf16(h4, h5);
                *(uint32_t*)(pL + col * 2)     = pack_bf16(l0, l1);
                *(uint32_t*)(pL + col * 2 + 4) = pack_bf16(l2, l3);
                *(uint32_t*)(pL + col * 2 + 8) = pack_bf16(l4, l5);
            }
        } else {
            int c0 = half * 64;
            const float* Arow = x + (size_t)gr * 128;
            for (int cc = c0; cc < c0 + 64; cc += 4) {
                float4 a = make_float4(0.f, 0.f, 0.f, 0.f);
                if (gr < M) a = *reinterpret_cast<const float4*>(Arow + cc);
                float v0 = silu(a.x), v1 = silu(a.y), v2 = silu(a.z), v3 = silu(a.w);
                __nv_bfloat16 h0, h1, h2, h3, l0, l1, l2, l3;
                split2(v0, h0, l0); split2(v1, h1, l1);
                split2(v2, h2, l2); split2(v3, h3, l3);
                *(uint32_t*)(pH + cc * 2)     = pack_bf16(h0, h1);
                *(uint32_t*)(pH + cc * 2 + 4) = pack_bf16(h2, h3);
                *(uint32_t*)(pL + cc * 2)     = pack_bf16(l0, l1);
                *(uint32_t*)(pL + cc * 2 + 4) = pack_bf16(l2, l3);
            }
        }
        cp_wait_all();
        __syncthreads();

        int ksteps = (c < 8) ? 6 : 8;
#pragma unroll 1
        for (int ks = 0; ks < ksteps; ks++) {
            uint32_t kb = (uint32_t)(ks * 16);
            uint32_t ah[2][4], al[2][4];
#pragma unroll
            for (int rt = 0; rt < 2; rt++) {
                uint32_t aoff = (((uint32_t)(rb * 32 + rt * 16) + aRowL) * WSTRIDE + kb + aK8) * 2;
                ldsm_x4(ah[rt], smBase + offAH + aoff);
                ldsm_x4(al[rt], smBase + offAL + aoff);
            }
            uint32_t bh[2][4], bl[2][4];
#pragma unroll
            for (int tp = 0; tp < 2; tp++) {
                uint32_t woff = (((uint32_t)(cb * 32 + tp * 16) + wN) * WSTRIDE + kb + wK8) * 2;
                ldsm_x4(bh[tp], smBase + offWh + woff);
                ldsm_x4(bl[tp], smBase + offWl + woff);
            }
            // product-major order: same-acc reuse distance = 8
#pragma unroll
            for (int rt = 0; rt < 2; rt++)
#pragma unroll
                for (int tp = 0; tp < 2; tp++) {
                    int t0 = rt * 4 + tp * 2;
                    mma_bf16(acc[t0],     ah[rt], bh[tp][0], bh[tp][1]);
                    mma_bf16(acc[t0 + 1], ah[rt], bh[tp][2], bh[tp][3]);
                }
#pragma unroll
            for (int rt = 0; rt < 2; rt++)
#pragma unroll
                for (int tp = 0; tp < 2; tp++) {
                    int t0 = rt * 4 + tp * 2;
                    mma_bf16(acc[t0],     ah[rt], bl[tp][0], bl[tp][1]);
                    mma_bf16(acc[t0 + 1], ah[rt], bl[tp][2], bl[tp][3]);
                }
#pragma unroll
            for (int rt = 0; rt < 2; rt++)
#pragma unroll
                for (int tp = 0; tp < 2; tp++) {
                    int t0 = rt * 4 + tp * 2;
                    mma_bf16(acc[t0],     al[rt], bh[tp][0], bh[tp][1]);
                    mma_bf16(acc[t0 + 1], al[rt], bh[tp][2], bh[tp][3]);
                }
        }
        __syncthreads();
    }

#pragma unroll
    for (int rt = 0; rt < 2; rt++) {
        int gr0 = row0 + rb * 32 + rt * 16 + (lane >> 2);
        int gr1 = gr0 + 8;
#pragma unroll
        for (int tp = 0; tp < 2; tp++) {
#pragma unroll
            for (int j = 0; j < 2; j++) {
                int col = cb * 32 + tp * 16 + j * 8 + (lane & 3) * 2;
                float* a = acc[rt * 4 + tp * 2 + j];
                if (gr0 < M) *reinterpret_cast<float2*>(out + (size_t)gr0 * 64 + col) = make_float2(a[0], a[1]);
                if (gr1 < M) *reinterpret_cast<float2*>(out + (size_t)gr1 * 64 + col) = make_float2(a[2], a[3]);
            }
        }
    }
}

// ---------------- KAN layer 2: f32x2 packed dual-output accumulation -------------
__global__ void kan2_kernel(const float* __restrict__ hin,
                            const float* __restrict__ spline,   // [2,64,8]
                            const float* __restrict__ scaler,   // [2,64]
                            const float* __restrict__ basew,    // [2,64]
                            float* __restrict__ out, int M)     // [M,2]
{
    __shared__ float sh[128][65];
    __shared__ __align__(8) unsigned long long sw2[64][8];
    __shared__ __align__(8) unsigned long long sb2[64];
    int tid = threadIdx.x;
    int row0 = blockIdx.x * 128;
    for (int idx = tid; idx < 512; idx += 128) {
        int f = idx >> 3, t = idx & 7;
        float w0 = spline[f * 8 + t] * scaler[f];
        float w1 = spline[512 + f * 8 + t] * scaler[64 + f];
        sw2[f][t] = pack_x2(w0, w1);
    }
    if (tid < 64) sb2[tid] = pack_x2(basew[tid], basew[64 + tid]);
    for (int idx = tid; idx < 128 * 64; idx += 128) {
        int r = idx >> 6, f = idx & 63;
        int gr = row0 + r;
        sh[r][f] = (gr < M) ? hin[(size_t)gr * 64 + f] : 0.f;
    }
    __syncthreads();
    int gr = row0 + tid;
    if (gr >= M) return;
    unsigned long long acc = 0ULL;
    for (int f = 0; f < 64; f++) {
        float xv = sh[tid][f];
        fma_x2(acc, dup_x2(silu(xv)), sb2[f]);
        float b[8];
        bspline8(xv, b);
#pragma unroll
        for (int t = 0; t < 8; t++) fma_x2(acc, dup_x2(b[t]), sw2[f][t]);
    }
    float o0, o1;
    unpack_x2(acc, o0, o1);
    *reinterpret_cast<float2*>(out + (size_t)gr * 2) = make_float2(o0, o1);
}

// ---------------- launch ----------------
extern "C" void kernel_launch(void* const* d_in, const int* in_sizes, int n_in,
                              void* d_out, int out_size)
{
    const float* x_email    = (const float*)d_in[0];
    const int*   ei_ue      = (const int*)d_in[1];
    const int*   ei_eu      = (const int*)d_in[2];
    const float* w_email    = (const float*)d_in[3];
    const float* b_email    = (const float*)d_in[4];
    const float* emb_user   = (const float*)d_in[5];
    const float* w_l1_ue_n  = (const float*)d_in[6];
    const float* b_l1_ue    = (const float*)d_in[7];
    const float* w_l1_ue_r  = (const float*)d_in[8];
    const float* w_l1_eu_n  = (const float*)d_in[9];
    const float* b_l1_eu    = (const float*)d_in[10];
    const float* w_l1_eu_r  = (const float*)d_in[11];
    const float* w_l2_ue_n  = (const float*)d_in[12];
    const float* b_l2_ue    = (const float*)d_in[13];
    const float* w_l2_ue_r  = (const float*)d_in[14];
    const float* kan1_base   = (const float*)d_in[18];
    const float* kan1_spline = (const float*)d_in[19];
    const float* kan1_scaler = (const float*)d_in[20];
    const float* kan2_base   = (const float*)d_in[22];
    const float* kan2_spline = (const float*)d_in[23];
    const float* kan2_scaler = (const float*)d_in[24];
    float* out = (float*)d_out;

    float *xe, *accE, *accE2, *e1, *accUx, *u1, *hbuf, *cntE, *cntU, *bias1, *gb2;
    cudaGetSymbolAddress((void**)&xe,    g_xe);
    cudaGetSymbolAddress((void**)&accE,  g_accE);
    cudaGetSymbolAddress((void**)&accE2, g_accE2);
    cudaGetSymbolAddress((void**)&e1,    g_e1);
    cudaGetSymbolAddress((void**)&accUx, g_accUx);
    cudaGetSymbolAddress((void**)&u1,    g_u1);
    cudaGetSymbolAddress((void**)&hbuf,  g_h);
    cudaGetSymbolAddress((void**)&cntE,  g_cntE);
    cudaGetSymbolAddress((void**)&cntU,  g_cntU);
    cudaGetSymbolAddress((void**)&bias1, g_bias1);
    cudaGetSymbolAddress((void**)&gb2,   g_gb2);
    __nv_bfloat16 *wh, *wl, *wch, *wcl, *k1wh, *k1wl;
    cudaGetSymbolAddress((void**)&wh,   g_wh);
    cudaGetSymbolAddress((void**)&wl,   g_wl);
    cudaGetSymbolAddress((void**)&wch,  g_wch);
    cudaGetSymbolAddress((void**)&wcl,  g_wcl);
    cudaGetSymbolAddress((void**)&k1wh, g_k1wh);
    cudaGetSymbolAddress((void**)&k1wl, g_k1wl);
    auto WH = [&](int m) { return wh + (size_t)m * 128 * WSTRIDE; };
    auto WL = [&](int m) { return wl + (size_t)m * 128 * WSTRIDE; };
    auto WCH = [&](int m) { return wch + (size_t)m * 128 * WSTRIDE; };
    auto WCL = [&](int m) { return wcl + (size_t)m * 128 * WSTRIDE; };

    const int gE = (NE + 127) / 128;   // 1563
    const int gU = (NU + 127) / 128;   // 782
    const int gScat = (NEDGE / 8 * 32 + 255) / 256;    // 15625
    const int gScat64 = (NEDGE / 16 * 32 + 255) / 256; // 7813

    const int SMEM_TC = (int)(6 * TILEB);
    const int SMEM_K1 = (int)(2 * TILEB + 2 * K1WT);
    cudaFuncSetAttribute(gemm_tc, cudaFuncAttributeMaxDynamicSharedMemorySize, SMEM_TC);
    cudaFuncSetAttribute(kan1_tc, cudaFuncAttributeMaxDynamicSharedMemorySize, SMEM_K1);

    init_kernel<<<4096, 256>>>(w_email, b_email, w_l1_ue_n, w_l1_ue_r, b_l1_ue,
                               w_l1_eu_n, w_l1_eu_r, w_l2_ue_n, w_l2_ue_r,
                               kan1_spline, kan1_scaler, kan1_base);
    scatter_kernel<<<gScat, 256>>>(ei_ue, ei_ue + NEDGE, emb_user, accE, cntE, 1);
    scatter64_kernel<<<gScat64, 256>>>(ei_eu, ei_eu + NEDGE, x_email, accUx, cntU);
    gemm_tc<<<gE, 256, SMEM_TC>>>(accE, 128, WH(0), WL(0),
                                  x_email, 64, WCH(0), WCL(0),
                                  bias1, cntE, nullptr, e1, NE);
    gemm_tc<<<gU, 256, SMEM_TC>>>(accUx, 64, WCH(1), WCL(1),
                                  emb_user, 128, WH(3), WL(3),
                                  b_l1_eu, cntU, gb2, u1, NU);
    scatter_kernel<<<gScat, 256>>>(ei_ue, ei_ue + NEDGE, u1, accE2, nullptr, 0);
    gemm_tc<<<gE, 256, SMEM_TC>>>(accE2, 128, WH(4), WL(4),
                                  e1, 128, WH(5), WL(5),
                                  b_l2_ue, cntE, nullptr, xe /*= e2*/, NE);
    kan1_tc<<<gE, 256, SMEM_K1>>>(xe, k1wh, k1wl, hbuf, NE);
    kan2_kernel<<<gE, 128>>>(hbuf, kan2_spline, kan2_scaler, kan2_base, out, NE);
}